// round 3
// baseline (speedup 1.0000x reference)
#include <cuda_runtime.h>
#include <cstdint>
#include <cstddef>

#define BATCH 64
#define SEQ   512
#define HID   1024
#define G4    4096
#define NCTA  128
#define OUT_ELEMS ((size_t)BATCH * SEQ * HID)

typedef unsigned long long u64t;

// Scratch (device globals — no allocation allowed).
static __device__ float g_xg[(size_t)SEQ * BATCH * G4];   // [t][b][g]
static __device__ float g_hbuf[2][BATCH * HID];           // ping-pong hidden state
static __device__ unsigned g_bar;                         // grid barrier counter

__global__ void reset_kernel() {
    int i = blockIdx.x * blockDim.x + threadIdx.x;
    if (i == 0) g_bar = 0u;
    if (i < BATCH * HID) g_hbuf[0][i] = 0.0f;
}

__device__ __forceinline__ void fma2(u64t& d, u64t a, u64t b) {
    asm("fma.rn.f32x2 %0, %1, %2, %0;" : "+l"(d) : "l"(a), "l"(b));
}
__device__ __forceinline__ float lof(u64t v) { return __uint_as_float((unsigned)v); }
__device__ __forceinline__ float hif(u64t v) { return __uint_as_float((unsigned)(v >> 32)); }
__device__ __forceinline__ float sigm(float x) { return 1.0f / (1.0f + __expf(-x)); }

// ---------------------------------------------------------------------------
// Projection GEMM: g_xg[s][b][:] = A[b*SEQ+s, :] @ W + (bx+bh)
// 64x64 tile, KC=32, 256 threads, 4 rows x 4 cols (cols n0+16j), f32x2 k-packed.
// ---------------------------------------------------------------------------
__global__ __launch_bounds__(256) void proj_kernel(const float* __restrict__ A,
                                                   const float* __restrict__ W,
                                                   const float* __restrict__ bx,
                                                   const float* __restrict__ bh) {
    __shared__ __align__(16) float sA[64 * 36];   // [m][k], k contiguous
    __shared__ __align__(16) float sB[64 * 34];   // [n][k], k contiguous

    const int tid  = threadIdx.x;
    const int row0 = blockIdx.y * 64;
    const int col0 = blockIdx.x * 64;

    const int m0 = (tid >> 4) * 4;
    const int n0 = tid & 15;              // cols n0 + 16*j

    const int la = tid >> 2;              // A-fill row
    const int kq = (tid & 3) * 8;         // A-fill k offset (2 x float4)
    const int lbn = tid & 63;             // B-fill col
    const int lbk = (tid >> 6) * 8;       // B-fill k base (8 rows)

    u64t acc[4][4] = {};

    for (int k0 = 0; k0 < HID; k0 += 32) {
        const float* ap = &A[(size_t)(row0 + la) * HID + k0 + kq];
        *(float4*)&sA[la * 36 + kq]     = *(const float4*)(ap);
        *(float4*)&sA[la * 36 + kq + 4] = *(const float4*)(ap + 4);
#pragma unroll
        for (int i = 0; i < 8; i++)
            sB[lbn * 34 + lbk + i] = W[(size_t)(k0 + lbk + i) * G4 + col0 + lbn];
        __syncthreads();
#pragma unroll
        for (int kk = 0; kk < 32; kk += 2) {
            u64t a0 = *(const u64t*)&sA[(m0 + 0) * 36 + kk];
            u64t a1 = *(const u64t*)&sA[(m0 + 1) * 36 + kk];
            u64t a2 = *(const u64t*)&sA[(m0 + 2) * 36 + kk];
            u64t a3 = *(const u64t*)&sA[(m0 + 3) * 36 + kk];
#pragma unroll
            for (int j = 0; j < 4; j++) {
                u64t b = *(const u64t*)&sB[(n0 + 16 * j) * 34 + kk];
                fma2(acc[0][j], a0, b);
                fma2(acc[1][j], a1, b);
                fma2(acc[2][j], a2, b);
                fma2(acc[3][j], a3, b);
            }
        }
        __syncthreads();
    }

#pragma unroll
    for (int r = 0; r < 4; r++) {
        int m = row0 + m0 + r;
        int b = m >> 9;               // / SEQ
        int s = m & (SEQ - 1);
        float* dst = &g_xg[((size_t)s * BATCH + b) * G4 + col0];
#pragma unroll
        for (int j = 0; j < 4; j++) {
            int col = col0 + n0 + 16 * j;
            dst[n0 + 16 * j] = lof(acc[r][j]) + hif(acc[r][j]) + bx[col] + bh[col];
        }
    }
}

// ---------------------------------------------------------------------------
// Persistent recurrence kernel: one launch runs all 512 steps of a layer.
// 128 CTAs (1/SM), CTA owns j in [j0,j0+8) -> 32 gate cols. Wh slice (128 KB)
// resident in smem the whole layer. Cell state c in registers.
// GEMM per step: M=64, N=32, K=1024, f32x2 k-packed, cols nA=t / nB=t+16.
// ---------------------------------------------------------------------------
#define SWH_STRIDE 1026
#define SH_STRIDE  132
#define SG_STRIDE  33
#define SMEM_FLOATS (32 * SWH_STRIDE + 64 * SH_STRIDE + 64 * SG_STRIDE)

__global__ __launch_bounds__(256, 1) void lstm_seq_kernel(const float* __restrict__ Wh,
                                                          float* __restrict__ hs,
                                                          float* __restrict__ hT,
                                                          float* __restrict__ cT) {
    extern __shared__ float sm[];
    float* sWh = sm;                        // [32][1026]
    float* sH  = sm + 32 * SWH_STRIDE;      // [64][132]
    float* sG  = sH + 64 * SH_STRIDE;       // [64][33]

    const int tid = threadIdx.x;
    const int j0  = blockIdx.x * 8;

    // Load this CTA's Wh slice once (32 gate columns x 1024 k).
    for (int u = tid; u < 32 * HID; u += 256) {
        int c = u & 31, k = u >> 5;
        int gcol = ((c >> 3) << 10) + j0 + (c & 7);
        sWh[c * SWH_STRIDE + k] = Wh[(size_t)k * G4 + gcol];
    }

    const int m0 = (tid >> 4) * 4;
    const int nA = tid & 15;
    const int nB = nA + 16;
    const int gcolA = ((nA >> 3) << 10) + j0 + (nA & 7);
    const int gcolB = ((nB >> 3) << 10) + j0 + (nB & 7);

    const int fb = tid >> 2;          // sH fill row
    const int fk = (tid & 3) * 32;    // sH fill k base

    float creg[2] = {0.0f, 0.0f};

    __syncthreads();

    unsigned target = NCTA;
    for (int t = 0; t < SEQ; t++) {
        const float* __restrict__ h_in = g_hbuf[t & 1];
        float* __restrict__ h_out      = g_hbuf[(t & 1) ^ 1];
        const float* __restrict__ xg_t = g_xg + (size_t)t * BATCH * G4;

        u64t acc[4][2] = {};

        for (int k0 = 0; k0 < HID; k0 += 128) {
            const float4* hp = (const float4*)&h_in[(size_t)fb * HID + k0 + fk];
#pragma unroll
            for (int i = 0; i < 8; i++)
                *(float4*)&sH[fb * SH_STRIDE + fk + i * 4] = __ldcg(hp + i);
            __syncthreads();
#pragma unroll
            for (int kk = 0; kk < 128; kk += 2) {
                u64t a0 = *(const u64t*)&sH[(m0 + 0) * SH_STRIDE + kk];
                u64t a1 = *(const u64t*)&sH[(m0 + 1) * SH_STRIDE + kk];
                u64t a2 = *(const u64t*)&sH[(m0 + 2) * SH_STRIDE + kk];
                u64t a3 = *(const u64t*)&sH[(m0 + 3) * SH_STRIDE + kk];
                u64t w0 = *(const u64t*)&sWh[nA * SWH_STRIDE + k0 + kk];
                u64t w1 = *(const u64t*)&sWh[nB * SWH_STRIDE + k0 + kk];
                fma2(acc[0][0], a0, w0); fma2(acc[0][1], a0, w1);
                fma2(acc[1][0], a1, w0); fma2(acc[1][1], a1, w1);
                fma2(acc[2][0], a2, w0); fma2(acc[2][1], a2, w1);
                fma2(acc[3][0], a3, w0); fma2(acc[3][1], a3, w1);
            }
            __syncthreads();
        }

        // gates = acc + xg, staged in shared
#pragma unroll
        for (int r = 0; r < 4; r++) {
            int m = m0 + r;
            sG[m * SG_STRIDE + nA] = lof(acc[r][0]) + hif(acc[r][0]) + xg_t[(size_t)m * G4 + gcolA];
            sG[m * SG_STRIDE + nB] = lof(acc[r][1]) + hif(acc[r][1]) + xg_t[(size_t)m * G4 + gcolB];
        }
        __syncthreads();

        // cell update: 512 (b,j) per CTA, 2 per thread, c in registers
#pragma unroll
        for (int q = 0; q < 2; q++) {
            int idx = q * 256 + tid;
            int bb  = idx >> 3;
            int jj  = idx & 7;
            int j   = j0 + jj;
            float gi = sG[bb * SG_STRIDE + jj];
            float gf = sG[bb * SG_STRIDE + 8 + jj];
            float gg = sG[bb * SG_STRIDE + 16 + jj];
            float go = sG[bb * SG_STRIDE + 24 + jj];
            float cn = sigm(gf) * creg[q] + sigm(gi) * tanhf(gg);
            float hn = sigm(go) * tanhf(cn);
            creg[q] = cn;
            h_out[bb * HID + j] = hn;
            hs[((size_t)bb * SEQ + t) * HID + j] = hn;
            if (t == SEQ - 1) {
                hT[bb * HID + j] = hn;
                cT[bb * HID + j] = cn;
            }
        }
        __syncthreads();

        // device-wide barrier (all 128 CTAs co-resident: 1 CTA/SM, 128 <= 148)
        if (tid == 0) {
            __threadfence();
            atomicAdd(&g_bar, 1u);
            while (*(volatile unsigned*)&g_bar < target) __nanosleep(32);
        }
        __syncthreads();
        target += NCTA;
    }
}

// ---------------------------------------------------------------------------
extern "C" void kernel_launch(void* const* d_in, const int* in_sizes, int n_in,
                              void* d_out, int out_size) {
    (void)in_sizes; (void)n_in; (void)out_size;
    const float* x     = (const float*)d_in[0];
    const float* Wx[2] = {(const float*)d_in[1], (const float*)d_in[5]};
    const float* bx[2] = {(const float*)d_in[2], (const float*)d_in[6]};
    const float* Wh[2] = {(const float*)d_in[3], (const float*)d_in[7]};
    const float* bh[2] = {(const float*)d_in[4], (const float*)d_in[8]};

    float* out = (float*)d_out;
    float* hs  = out;                          // (B,S,H): layer0 scratch, then final layer1 output
    float* hT  = out + OUT_ELEMS;              // (L,B,H)
    float* cT  = hT + 2 * BATCH * HID;         // (L,B,H)

    static int smem_set = 0;
    if (!smem_set) {
        cudaFuncSetAttribute(lstm_seq_kernel, cudaFuncAttributeMaxDynamicSharedMemorySize,
                             SMEM_FLOATS * sizeof(float));
        smem_set = 1;
    }

    dim3 pgrid(G4 / 64, (BATCH * SEQ) / 64);

    for (int l = 0; l < 2; l++) {
        const float* A = (l == 0) ? x : hs;    // layer1 reads layer0's h sequence from d_out
        proj_kernel<<<pgrid, 256>>>(A, Wx[l], bx[l], bh[l]);
        reset_kernel<<<(BATCH * HID + 255) / 256, 256>>>();
        lstm_seq_kernel<<<NCTA, 256, SMEM_FLOATS * sizeof(float)>>>(
            Wh[l], hs, hT + l * BATCH * HID, cT + l * BATCH * HID);
    }
}

// round 5
// speedup vs baseline: 1.5176x; 1.5176x over previous
#include <cuda_runtime.h>
#include <cstdint>
#include <cstddef>

#define BATCH 64
#define SEQ   512
#define HID   1024
#define G4    4096
#define NCTA  128
#define OUT_ELEMS ((size_t)BATCH * SEQ * HID)

typedef unsigned long long u64t;

// Scratch (device globals — no allocation allowed).
static __device__ float g_xg[(size_t)SEQ * BATCH * G4];   // [t][b][g]
static __device__ float g_hbuf[2][BATCH * HID];           // ping-pong hidden state
static __device__ unsigned g_bar;                         // grid barrier counter

__global__ void reset_kernel() {
    int i = blockIdx.x * blockDim.x + threadIdx.x;
    if (i == 0) g_bar = 0u;
    if (i < BATCH * HID) g_hbuf[0][i] = 0.0f;
}

__device__ __forceinline__ void fma2(u64t& d, u64t a, u64t b) {
    asm("fma.rn.f32x2 %0, %1, %2, %0;" : "+l"(d) : "l"(a), "l"(b));
}
__device__ __forceinline__ float lof(u64t v) { return __uint_as_float((unsigned)v); }
__device__ __forceinline__ float hif(u64t v) { return __uint_as_float((unsigned)(v >> 32)); }
__device__ __forceinline__ float sigm(float x) { return 1.0f / (1.0f + __expf(-x)); }

__device__ __forceinline__ void cpa16(uint32_t smem_dst, const void* gsrc) {
    asm volatile("cp.async.cg.shared.global [%0], [%1], 16;" :: "r"(smem_dst), "l"(gsrc));
}
__device__ __forceinline__ void cpa_commit() { asm volatile("cp.async.commit_group;"); }
__device__ __forceinline__ void cpa_wait0()  { asm volatile("cp.async.wait_group 0;" ::: "memory"); }

// ---------------------------------------------------------------------------
// Projection GEMM: g_xg[s][b][:] = A[b*SEQ+s, :] @ W + (bx+bh)
// CTA tile 64(M) x 128(N), KC=32, double-buffered. 256 thr, 4x8/thread,
// f32x2 k-packed, conflict-free LDS.64 operand loads.
// ---------------------------------------------------------------------------
#define PA_STR 36
#define PB_STR 34
#define PSTAGE (64 * PA_STR + 128 * PB_STR)     // 6656 floats per stage
#define PSMEM  (2 * PSTAGE)                     // 13312 floats = 53248 B

__global__ __launch_bounds__(256, 2) void proj_kernel(const float* __restrict__ A,
                                                      const float* __restrict__ W,
                                                      const float* __restrict__ bx,
                                                      const float* __restrict__ bh) {
    extern __shared__ float psm[];

    const int tid  = threadIdx.x;
    const int row0 = blockIdx.y * 64;
    const int col0 = blockIdx.x * 128;

    const int m0 = (tid >> 4) * 4;        // 4 consecutive rows
    const int nq = tid & 15;              // cols nq + 16*j, j=0..7

    const int la = tid >> 2;              // A-fill row
    const int kq = (tid & 3) * 8;         // A-fill k offset
    const int bn = tid & 127;             // B-fill col
    const int bk = tid >> 7;              // B-fill k parity

    const uint32_t smem_u32 = (uint32_t)__cvta_generic_to_shared(psm);

    u64t acc[4][8];
#pragma unroll
    for (int r = 0; r < 4; r++)
#pragma unroll
        for (int j = 0; j < 8; j++) acc[r][j] = 0ull;

    float rB[16];
    const float* arow = &A[(size_t)(row0 + la) * HID + kq];

    // prologue: fill stage 0 (k0 = 0)
    {
        uint32_t adst = smem_u32 + (la * PA_STR + kq) * 4;
        cpa16(adst, arow);
        cpa16(adst + 16, arow + 4);
#pragma unroll
        for (int it = 0; it < 16; it++)
            rB[it] = W[(size_t)(it * 2 + bk) * G4 + col0 + bn];
        float* sB0 = psm + 64 * PA_STR;
#pragma unroll
        for (int it = 0; it < 16; it++)
            sB0[bn * PB_STR + it * 2 + bk] = rB[it];
        cpa_commit();
        cpa_wait0();
        __syncthreads();
    }

#pragma unroll 1
    for (int c = 0; c < 32; c++) {
        const int cur = c & 1, nxt = cur ^ 1;
        const float* sA = psm + cur * PSTAGE;
        const float* sB = psm + cur * PSTAGE + 64 * PA_STR;

        if (c < 31) {   // prefetch next chunk: A via cp.async, B into regs
            int k0n = (c + 1) * 32;
            uint32_t adst = smem_u32 + (nxt * PSTAGE + la * PA_STR + kq) * 4;
            cpa16(adst, arow + k0n);
            cpa16(adst + 16, arow + k0n + 4);
            cpa_commit();
#pragma unroll
            for (int it = 0; it < 16; it++)
                rB[it] = W[(size_t)(k0n + it * 2 + bk) * G4 + col0 + bn];
        }

#pragma unroll 16
        for (int kk = 0; kk < 32; kk += 2) {
            u64t a0 = *(const u64t*)&sA[(m0 + 0) * PA_STR + kk];
            u64t a1 = *(const u64t*)&sA[(m0 + 1) * PA_STR + kk];
            u64t a2 = *(const u64t*)&sA[(m0 + 2) * PA_STR + kk];
            u64t a3 = *(const u64t*)&sA[(m0 + 3) * PA_STR + kk];
#pragma unroll
            for (int j = 0; j < 8; j++) {
                u64t b = *(const u64t*)&sB[(nq + 16 * j) * PB_STR + kk];
                fma2(acc[0][j], a0, b);
                fma2(acc[1][j], a1, b);
                fma2(acc[2][j], a2, b);
                fma2(acc[3][j], a3, b);
            }
        }

        if (c < 31) {
            float* sBn = psm + nxt * PSTAGE + 64 * PA_STR;
#pragma unroll
            for (int it = 0; it < 16; it++)
                sBn[bn * PB_STR + it * 2 + bk] = rB[it];
            cpa_wait0();
        }
        __syncthreads();
    }

#pragma unroll
    for (int r = 0; r < 4; r++) {
        int m = row0 + m0 + r;
        int b = m >> 9;               // / SEQ
        int s = m & (SEQ - 1);
        float* dst = &g_xg[((size_t)s * BATCH + b) * G4 + col0];
#pragma unroll
        for (int j = 0; j < 8; j++) {
            int col = col0 + nq + 16 * j;
            dst[nq + 16 * j] = lof(acc[r][j]) + hif(acc[r][j]) + bx[col] + bh[col];
        }
    }
}

// ---------------------------------------------------------------------------
// Persistent recurrence kernel: 128 CTAs (1/SM), all 512 steps in one launch.
// CTA owns j in [j0,j0+8) -> 32 gate cols. Wh slice (131 KB) smem-resident.
// Split-K x2: group g (128 thr) computes k-half [g*512,(g+1)*512), 4x4 tile
// with interleaved rows m0+{0,16,32,48}; partials combined via smem.
// Cell state in registers. f32x2 k-packed throughout.
// ---------------------------------------------------------------------------
#define SWH_STR 1026
#define SH_STR  136
#define SG_STR  33
#define SMEM_FLOATS (32 * SWH_STR + 2 * 64 * SH_STR + 2 * 64 * SG_STR)  // 54464

__global__ __launch_bounds__(256, 1) void lstm_seq_kernel(const float* __restrict__ Wh,
                                                          float* __restrict__ hs,
                                                          float* __restrict__ hT,
                                                          float* __restrict__ cT) {
    extern __shared__ float sm[];
    float* sWh = sm;                         // [32][1026]
    float* sH  = sm + 32 * SWH_STR;          // 2 x [64][136] (per-group chunk buffer)
    float* sG  = sH + 2 * 64 * SH_STR;       // 2 x [64][33]  (per-group partials)

    const int tid = threadIdx.x;
    const int j0  = blockIdx.x * 8;

    // Wh slice fill (once per layer): 32 cols x 1024 k
#pragma unroll 4
    for (int it = 0; it < 128; it++) {
        int idx = it * 256 + tid;
        int c = idx & 31, k = idx >> 5;
        int gcol = ((c >> 3) << 10) + j0 + (c & 7);
        sWh[c * SWH_STR + k] = Wh[(size_t)k * G4 + gcol];
    }

    const int grp = tid >> 7;                // k-split group
    const int gt  = tid & 127;
    const int m0  = gt >> 3;                 // rows m0 + 16u
    const int nq  = gt & 7;                  // cols nq + 8j
    const int kb  = grp << 9;                // 0 or 512
    float* sHg = sH + grp * 64 * SH_STR;
    float* sGg = sG + grp * 64 * SG_STR;
    const uint32_t sHg_u32 = (uint32_t)__cvta_generic_to_shared(sHg);

    float creg[2] = {0.0f, 0.0f};
    __syncthreads();

    unsigned target = NCTA;
    for (int t = 0; t < SEQ; t++) {
        const float* __restrict__ h_in = g_hbuf[t & 1];
        float* __restrict__ h_out      = g_hbuf[(t & 1) ^ 1];
        const float* __restrict__ xg_t = g_xg + (size_t)t * BATCH * G4;

        // prefetch xg operands for the cell update (hidden behind the GEMM)
        float xr[2][4];
#pragma unroll
        for (int q = 0; q < 2; q++) {
            int idx = q * 256 + tid;
            int bb = idx >> 3, jj = idx & 7;
#pragma unroll
            for (int g = 0; g < 4; g++)
                xr[q][g] = __ldg(&xg_t[(size_t)bb * G4 + (g << 10) + j0 + jj]);
        }

        u64t acc[4][4];
#pragma unroll
        for (int u = 0; u < 4; u++)
#pragma unroll
            for (int j = 0; j < 4; j++) acc[u][j] = 0ull;

#pragma unroll 1
        for (int ch = 0; ch < 4; ch++) {
            const float* hsrc = h_in + kb + ch * 128;
            // fill this group's 64x128 h chunk (L2-direct, coherence-safe)
#pragma unroll
            for (int i = 0; i < 16; i++) {
                int idx = i * 128 + gt;
                int row = idx >> 5;
                int f4  = (idx & 31) * 4;
                cpa16(sHg_u32 + (row * SH_STR + f4) * 4, hsrc + (size_t)row * HID + f4);
            }
            cpa_commit();
            cpa_wait0();
            __syncthreads();

            const float* wbase = sWh + kb + ch * 128;
#pragma unroll 16
            for (int kk = 0; kk < 128; kk += 2) {
                u64t a0 = *(const u64t*)&sHg[(m0     ) * SH_STR + kk];
                u64t a1 = *(const u64t*)&sHg[(m0 + 16) * SH_STR + kk];
                u64t a2 = *(const u64t*)&sHg[(m0 + 32) * SH_STR + kk];
                u64t a3 = *(const u64t*)&sHg[(m0 + 48) * SH_STR + kk];
#pragma unroll
                for (int j = 0; j < 4; j++) {
                    u64t w = *(const u64t*)&wbase[(nq + 8 * j) * SWH_STR + kk];
                    fma2(acc[0][j], a0, w);
                    fma2(acc[1][j], a1, w);
                    fma2(acc[2][j], a2, w);
                    fma2(acc[3][j], a3, w);
                }
            }
            __syncthreads();
        }

        // stage this group's partials
#pragma unroll
        for (int u = 0; u < 4; u++)
#pragma unroll
            for (int j = 0; j < 4; j++)
                sGg[(m0 + 16 * u) * SG_STR + nq + 8 * j] = lof(acc[u][j]) + hif(acc[u][j]);
        __syncthreads();

        // cell update: combine partials + xg; c stays in registers
#pragma unroll
        for (int q = 0; q < 2; q++) {
            int idx = q * 256 + tid;
            int bb = idx >> 3, jj = idx & 7;
            int j  = j0 + jj;
            float gi = sG[bb * SG_STR + jj]      + sG[(64 + bb) * SG_STR + jj]      + xr[q][0];
            float gf = sG[bb * SG_STR + 8 + jj]  + sG[(64 + bb) * SG_STR + 8 + jj]  + xr[q][1];
            float gg = sG[bb * SG_STR + 16 + jj] + sG[(64 + bb) * SG_STR + 16 + jj] + xr[q][2];
            float go = sG[bb * SG_STR + 24 + jj] + sG[(64 + bb) * SG_STR + 24 + jj] + xr[q][3];
            float cn = sigm(gf) * creg[q] + sigm(gi) * tanhf(gg);
            float hn = sigm(go) * tanhf(cn);
            creg[q] = cn;
            h_out[bb * HID + j] = hn;
            hs[((size_t)bb * SEQ + t) * HID + j] = hn;
            if (t == SEQ - 1) {
                hT[bb * HID + j] = hn;
                cT[bb * HID + j] = cn;
            }
        }

        // device-wide barrier (128 CTAs co-resident, 1/SM).
        // Every thread fences its h_out stores to device scope, then the CTA
        // syncs, then one thread arrives + spins. This orders ALL warps'
        // stores before any other CTA passes the barrier.
        __threadfence();
        __syncthreads();
        if (tid == 0) {
            atomicAdd(&g_bar, 1u);
            while (*(volatile unsigned*)&g_bar < target) __nanosleep(64);
        }
        __syncthreads();
        target += NCTA;
    }
}

// ---------------------------------------------------------------------------
extern "C" void kernel_launch(void* const* d_in, const int* in_sizes, int n_in,
                              void* d_out, int out_size) {
    (void)in_sizes; (void)n_in; (void)out_size;
    const float* x     = (const float*)d_in[0];
    const float* Wx[2] = {(const float*)d_in[1], (const float*)d_in[5]};
    const float* bx[2] = {(const float*)d_in[2], (const float*)d_in[6]};
    const float* Wh[2] = {(const float*)d_in[3], (const float*)d_in[7]};
    const float* bh[2] = {(const float*)d_in[4], (const float*)d_in[8]};

    float* out = (float*)d_out;
    float* hs  = out;                          // (B,S,H): layer0 scratch, then final layer1 output
    float* hT  = out + OUT_ELEMS;              // (L,B,H)
    float* cT  = hT + 2 * BATCH * HID;         // (L,B,H)

    static int attr_set = 0;
    if (!attr_set) {
        cudaFuncSetAttribute(lstm_seq_kernel, cudaFuncAttributeMaxDynamicSharedMemorySize,
                             SMEM_FLOATS * sizeof(float));
        cudaFuncSetAttribute(proj_kernel, cudaFuncAttributeMaxDynamicSharedMemorySize,
                             PSMEM * sizeof(float));
        attr_set = 1;
    }

    dim3 pgrid(G4 / 128, (BATCH * SEQ) / 64);

    for (int l = 0; l < 2; l++) {
        const float* A = (l == 0) ? x : hs;    // layer1 reads layer0's h sequence from d_out
        proj_kernel<<<pgrid, 256, PSMEM * sizeof(float)>>>(A, Wx[l], bx[l], bh[l]);
        reset_kernel<<<(BATCH * HID + 255) / 256, 256>>>();
        lstm_seq_kernel<<<NCTA, 256, SMEM_FLOATS * sizeof(float)>>>(
            Wh[l], hs, hT + l * BATCH * HID, cT + l * BATCH * HID);
    }
}

// round 7
// speedup vs baseline: 1.7881x; 1.1782x over previous
#include <cuda_runtime.h>
#include <mma.h>
#include <cstdint>
#include <cstddef>

using namespace nvcuda;

#define BATCH 64
#define SEQ   512
#define HID   1024
#define G4    4096
#define NCTA  128
#define OUT_ELEMS ((size_t)BATCH * SEQ * HID)

typedef unsigned long long u64t;

// Scratch (device globals — no allocation allowed).
static __device__ float g_xg[(size_t)SEQ * BATCH * G4];   // [t][b][g]
static __device__ float g_xa[(size_t)BATCH * SEQ * HID];  // tf32-rounded activations
static __device__ float g_wr[(size_t)HID * G4];           // tf32-rounded W [k][n]
static __device__ float g_hbuf[2][BATCH * HID];           // ping-pong hidden state
static __device__ unsigned g_bar;                         // grid barrier counter

__global__ void reset_kernel() {
    int i = blockIdx.x * blockDim.x + threadIdx.x;
    if (i == 0) g_bar = 0u;
    if (i < BATCH * HID) g_hbuf[0][i] = 0.0f;
}

__device__ __forceinline__ void fma2(u64t& d, u64t a, u64t b) {
    asm("fma.rn.f32x2 %0, %1, %2, %0;" : "+l"(d) : "l"(a), "l"(b));
}
__device__ __forceinline__ float lof(u64t v) { return __uint_as_float((unsigned)v); }
__device__ __forceinline__ float hif(u64t v) { return __uint_as_float((unsigned)(v >> 32)); }
__device__ __forceinline__ float sigm(float x) { return 1.0f / (1.0f + __expf(-x)); }

__device__ __forceinline__ void cpa16(uint32_t smem_dst, const void* gsrc) {
    asm volatile("cp.async.cg.shared.global [%0], [%1], 16;" :: "r"(smem_dst), "l"(gsrc));
}
__device__ __forceinline__ void cpa_commit() { asm volatile("cp.async.commit_group;"); }
__device__ __forceinline__ void cpa_wait0()  { asm volatile("cp.async.wait_group 0;" ::: "memory"); }

__device__ __forceinline__ float totf32(float x) {
    unsigned u;
    asm("cvt.rna.tf32.f32 %0, %1;" : "=r"(u) : "f"(x));
    return __uint_as_float(u);
}

// ---------------------------------------------------------------------------
// Pre-pass 1: elementwise tf32 rounding of activations -> g_xa.
// ---------------------------------------------------------------------------
__global__ __launch_bounds__(256) void conv_a_kernel(const float* __restrict__ in) {
    size_t i = (size_t)blockIdx.x * 256 + threadIdx.x;
    float4 v = ((const float4*)in)[i];
    v.x = totf32(v.x); v.y = totf32(v.y); v.z = totf32(v.z); v.w = totf32(v.w);
    ((float4*)g_xa)[i] = v;
}

// ---------------------------------------------------------------------------
// Pre-pass 2: elementwise tf32 rounding of W [k][n] -> g_wr (same layout).
// ---------------------------------------------------------------------------
__global__ __launch_bounds__(256) void conv_w_kernel(const float* __restrict__ W) {
    size_t i = (size_t)blockIdx.x * 256 + threadIdx.x;
    float4 v = ((const float4*)W)[i];
    v.x = totf32(v.x); v.y = totf32(v.y); v.z = totf32(v.z); v.w = totf32(v.w);
    ((float4*)g_wr)[i] = v;
}

// ---------------------------------------------------------------------------
// wmma-tf32 projection: g_xg[s][b][:] = A @ W + (bx+bh)
// CTA 128x128, KC=32, double-buffered cp.async. 8 warps: 4(M) x 2(N),
// warp tile 32x64 = 2x4 wmma m16n16k8 fragments. Inputs pre-rounded to tf32,
// so no per-fragment conversion needed (HW truncation is identity).
// ---------------------------------------------------------------------------
#define PM 128
#define PN 128
#define PKC 32
#define SA_STR 36
#define SB_STR 132
#define PSTG (PM * SA_STR + PKC * SB_STR)        // 4608 + 4224 = 8832 floats
#define EP_STR 132
#define PJ_SMEM_FLOATS (2 * PSTG + PN)           // stages + bias = 17792 floats
#define PJ_SMEM_BYTES (PJ_SMEM_FLOATS * 4)       // 71168 B

__device__ __forceinline__ void proj_fill(uint32_t stg_u32,
                                          const float* __restrict__ a_r0,
                                          const float* __restrict__ w_c0,
                                          int k0, int tid) {
    uint32_t aB = stg_u32;
    uint32_t bB = stg_u32 + PM * SA_STR * 4;
#pragma unroll
    for (int i = 0; i < 4; i++) {          // A: 128 rows x 32 f32 = 1024 f4
        int u = tid + 256 * i;
        int r = u >> 3, f = u & 7;
        cpa16(aB + (r * SA_STR + f * 4) * 4, a_r0 + (size_t)r * HID + k0 + f * 4);
    }
#pragma unroll
    for (int i = 0; i < 4; i++) {          // B: 32 rows x 128 f32 = 1024 f4
        int u = tid + 256 * i;
        int r = u >> 5, f = u & 31;
        cpa16(bB + (r * SB_STR + f * 4) * 4, w_c0 + (size_t)(k0 + r) * G4 + f * 4);
    }
}

__global__ __launch_bounds__(256, 2) void proj_wmma_kernel(const float* __restrict__ bx,
                                                           const float* __restrict__ bh) {
    extern __shared__ float ps[];
    float* sBias = ps + 2 * PSTG;

    const int tid = threadIdx.x;
    const int wid = tid >> 5;
    const int wm  = wid & 3;               // 4 warps along M (32 rows each)
    const int wn  = wid >> 2;              // 2 warps along N (64 cols each)

    const int col0 = blockIdx.x * PN;      // x fast-varying: A-tile reuse in L2
    const int row0 = blockIdx.y * PM;

    const uint32_t ps_u32 = (uint32_t)__cvta_generic_to_shared(ps);
    const float* a_r0 = g_xa + (size_t)row0 * HID;
    const float* w_c0 = g_wr + col0;

    if (tid < PN) sBias[tid] = bx[col0 + tid] + bh[col0 + tid];

    wmma::fragment<wmma::accumulator, 16, 16, 8, float> acc[2][4];
#pragma unroll
    for (int mt = 0; mt < 2; mt++)
#pragma unroll
        for (int nt = 0; nt < 4; nt++) wmma::fill_fragment(acc[mt][nt], 0.0f);

    // prologue: chunk 0 -> stage 0
    proj_fill(ps_u32, a_r0, w_c0, 0, tid);
    cpa_commit();
    cpa_wait0();
    __syncthreads();

#pragma unroll 1
    for (int c = 0; c < HID / PKC; c++) {
        const int cs = c & 1, ns = cs ^ 1;
        const float* sA = ps + cs * PSTG;
        const float* sB = sA + PM * SA_STR;

        if (c < HID / PKC - 1) {
            proj_fill(ps_u32 + ns * PSTG * 4, a_r0, w_c0, (c + 1) * PKC, tid);
            cpa_commit();
        }

#pragma unroll
        for (int kt = 0; kt < 4; kt++) {
            wmma::fragment<wmma::matrix_a, 16, 16, 8, wmma::precision::tf32, wmma::row_major> af[2];
            wmma::load_matrix_sync(af[0], sA + (wm * 32 +  0) * SA_STR + kt * 8, SA_STR);
            wmma::load_matrix_sync(af[1], sA + (wm * 32 + 16) * SA_STR + kt * 8, SA_STR);
#pragma unroll
            for (int nt = 0; nt < 4; nt++) {
                wmma::fragment<wmma::matrix_b, 16, 16, 8, wmma::precision::tf32, wmma::row_major> bf;
                wmma::load_matrix_sync(bf, sB + (kt * 8) * SB_STR + wn * 64 + nt * 16, SB_STR);
                wmma::mma_sync(acc[0][nt], af[0], bf, acc[0][nt]);
                wmma::mma_sync(acc[1][nt], af[1], bf, acc[1][nt]);
            }
        }

        cpa_wait0();
        __syncthreads();
    }

    // epilogue: stage accum in smem (reuse stage area), add bias, store.
    float* sEpi = ps;                      // [128][EP_STR]
#pragma unroll
    for (int mt = 0; mt < 2; mt++)
#pragma unroll
        for (int nt = 0; nt < 4; nt++)
            wmma::store_matrix_sync(sEpi + (wm * 32 + mt * 16) * EP_STR + wn * 64 + nt * 16,
                                    acc[mt][nt], EP_STR, wmma::mem_row_major);
    __syncthreads();

    const int r    = tid >> 1;             // row 0..127
    const int half = (tid & 1) * 64;       // col half
    const int m = row0 + r;
    const int b = m >> 9;                  // / SEQ
    const int s = m & (SEQ - 1);
    float* dst = &g_xg[((size_t)s * BATCH + b) * G4 + col0 + half];
#pragma unroll
    for (int j = 0; j < 64; j += 4) {
        float4 v = *(float4*)&sEpi[r * EP_STR + half + j];
        v.x += sBias[half + j + 0];
        v.y += sBias[half + j + 1];
        v.z += sBias[half + j + 2];
        v.w += sBias[half + j + 3];
        *(float4*)&dst[j] = v;
    }
}

// ---------------------------------------------------------------------------
// Persistent recurrence kernel: unchanged from the passing round-5 version.
// ---------------------------------------------------------------------------
#define SWH_STR 1026
#define SH_STR  136
#define SG_STR  33
#define SMEM_FLOATS (32 * SWH_STR + 2 * 64 * SH_STR + 2 * 64 * SG_STR)  // 54464

__global__ __launch_bounds__(256, 1) void lstm_seq_kernel(const float* __restrict__ Wh,
                                                          float* __restrict__ hs,
                                                          float* __restrict__ hT,
                                                          float* __restrict__ cT) {
    extern __shared__ float sm[];
    float* sWh = sm;                         // [32][1026]
    float* sH  = sm + 32 * SWH_STR;          // 2 x [64][136]
    float* sG  = sH + 2 * 64 * SH_STR;       // 2 x [64][33]

    const int tid = threadIdx.x;
    const int j0  = blockIdx.x * 8;

#pragma unroll 4
    for (int it = 0; it < 128; it++) {
        int idx = it * 256 + tid;
        int c = idx & 31, k = idx >> 5;
        int gcol = ((c >> 3) << 10) + j0 + (c & 7);
        sWh[c * SWH_STR + k] = Wh[(size_t)k * G4 + gcol];
    }

    const int grp = tid >> 7;
    const int gt  = tid & 127;
    const int m0  = gt >> 3;
    const int nq  = gt & 7;
    const int kb  = grp << 9;
    float* sHg = sH + grp * 64 * SH_STR;
    float* sGg = sG + grp * 64 * SG_STR;
    const uint32_t sHg_u32 = (uint32_t)__cvta_generic_to_shared(sHg);

    float creg[2] = {0.0f, 0.0f};
    __syncthreads();

    unsigned target = NCTA;
    for (int t = 0; t < SEQ; t++) {
        const float* __restrict__ h_in = g_hbuf[t & 1];
        float* __restrict__ h_out      = g_hbuf[(t & 1) ^ 1];
        const float* __restrict__ xg_t = g_xg + (size_t)t * BATCH * G4;

        float xr[2][4];
#pragma unroll
        for (int q = 0; q < 2; q++) {
            int idx = q * 256 + tid;
            int bb = idx >> 3, jj = idx & 7;
#pragma unroll
            for (int g = 0; g < 4; g++)
                xr[q][g] = __ldg(&xg_t[(size_t)bb * G4 + (g << 10) + j0 + jj]);
        }

        u64t acc[4][4];
#pragma unroll
        for (int u = 0; u < 4; u++)
#pragma unroll
            for (int j = 0; j < 4; j++) acc[u][j] = 0ull;

#pragma unroll 1
        for (int ch = 0; ch < 4; ch++) {
            const float* hsrc = h_in + kb + ch * 128;
#pragma unroll
            for (int i = 0; i < 16; i++) {
                int idx = i * 128 + gt;
                int row = idx >> 5;
                int f4  = (idx & 31) * 4;
                cpa16(sHg_u32 + (row * SH_STR + f4) * 4, hsrc + (size_t)row * HID + f4);
            }
            cpa_commit();
            cpa_wait0();
            __syncthreads();

            const float* wbase = sWh + kb + ch * 128;
#pragma unroll 16
            for (int kk = 0; kk < 128; kk += 2) {
                u64t a0 = *(const u64t*)&sHg[(m0     ) * SH_STR + kk];
                u64t a1 = *(const u64t*)&sHg[(m0 + 16) * SH_STR + kk];
                u64t a2 = *(const u64t*)&sHg[(m0 + 32) * SH_STR + kk];
                u64t a3 = *(const u64t*)&sHg[(m0 + 48) * SH_STR + kk];
#pragma unroll
                for (int j = 0; j < 4; j++) {
                    u64t w = *(const u64t*)&wbase[(nq + 8 * j) * SWH_STR + kk];
                    fma2(acc[0][j], a0, w);
                    fma2(acc[1][j], a1, w);
                    fma2(acc[2][j], a2, w);
                    fma2(acc[3][j], a3, w);
                }
            }
            __syncthreads();
        }

#pragma unroll
        for (int u = 0; u < 4; u++)
#pragma unroll
            for (int j = 0; j < 4; j++)
                sGg[(m0 + 16 * u) * SG_STR + nq + 8 * j] = lof(acc[u][j]) + hif(acc[u][j]);
        __syncthreads();

#pragma unroll
        for (int q = 0; q < 2; q++) {
            int idx = q * 256 + tid;
            int bb = idx >> 3, jj = idx & 7;
            int j  = j0 + jj;
            float gi = sG[bb * SG_STR + jj]      + sG[(64 + bb) * SG_STR + jj]      + xr[q][0];
            float gf = sG[bb * SG_STR + 8 + jj]  + sG[(64 + bb) * SG_STR + 8 + jj]  + xr[q][1];
            float gg = sG[bb * SG_STR + 16 + jj] + sG[(64 + bb) * SG_STR + 16 + jj] + xr[q][2];
            float go = sG[bb * SG_STR + 24 + jj] + sG[(64 + bb) * SG_STR + 24 + jj] + xr[q][3];
            float cn = sigm(gf) * creg[q] + sigm(gi) * tanhf(gg);
            float hn = sigm(go) * tanhf(cn);
            creg[q] = cn;
            h_out[bb * HID + j] = hn;
            hs[((size_t)bb * SEQ + t) * HID + j] = hn;
            if (t == SEQ - 1) {
                hT[bb * HID + j] = hn;
                cT[bb * HID + j] = cn;
            }
        }

        __threadfence();
        __syncthreads();
        if (tid == 0) {
            atomicAdd(&g_bar, 1u);
            while (*(volatile unsigned*)&g_bar < target) __nanosleep(64);
        }
        __syncthreads();
        target += NCTA;
    }
}

// ---------------------------------------------------------------------------
extern "C" void kernel_launch(void* const* d_in, const int* in_sizes, int n_in,
                              void* d_out, int out_size) {
    (void)in_sizes; (void)n_in; (void)out_size;
    const float* x     = (const float*)d_in[0];
    const float* Wx[2] = {(const float*)d_in[1], (const float*)d_in[5]};
    const float* bx[2] = {(const float*)d_in[2], (const float*)d_in[6]};
    const float* Wh[2] = {(const float*)d_in[3], (const float*)d_in[7]};
    const float* bh[2] = {(const float*)d_in[4], (const float*)d_in[8]};

    float* out = (float*)d_out;
    float* hs  = out;                          // (B,S,H): layer0 scratch, then final layer1 output
    float* hT  = out + OUT_ELEMS;              // (L,B,H)
    float* cT  = hT + 2 * BATCH * HID;         // (L,B,H)

    static int attr_set = 0;
    if (!attr_set) {
        cudaFuncSetAttribute(lstm_seq_kernel, cudaFuncAttributeMaxDynamicSharedMemorySize,
                             SMEM_FLOATS * sizeof(float));
        cudaFuncSetAttribute(proj_wmma_kernel, cudaFuncAttributeMaxDynamicSharedMemorySize,
                             PJ_SMEM_BYTES);
        attr_set = 1;
    }

    dim3 tgrid(G4 / PN, (BATCH * SEQ) / PM);   // (32, 256)

    for (int l = 0; l < 2; l++) {
        const float* A = (l == 0) ? x : hs;    // layer1 reads layer0's h sequence from d_out
        conv_a_kernel<<<(int)((OUT_ELEMS) / 1024), 256>>>(A);
        conv_w_kernel<<<(HID * G4) / 1024, 256>>>(Wx[l]);
        proj_wmma_kernel<<<tgrid, 256, PJ_SMEM_BYTES>>>(bx[l], bh[l]);
        reset_kernel<<<(BATCH * HID + 255) / 256, 256>>>();
        lstm_seq_kernel<<<NCTA, 256, SMEM_FLOATS * sizeof(float)>>>(
            Wh[l], hs, hT + l * BATCH * HID, cT + l * BATCH * HID);
    }
}

// round 8
// speedup vs baseline: 2.0522x; 1.1477x over previous
#include <cuda_runtime.h>
#include <mma.h>
#include <cstdint>
#include <cstddef>

using namespace nvcuda;

#define BATCH 64
#define SEQ   512
#define HID   1024
#define G4    4096
#define NCTA  128
#define OUT_ELEMS ((size_t)BATCH * SEQ * HID)

// Scratch (device globals — no allocation allowed).
static __device__ float g_xg[(size_t)SEQ * BATCH * G4];   // [t][b][g]
static __device__ float g_xa[(size_t)BATCH * SEQ * HID];  // tf32-rounded activations
static __device__ float g_wr[(size_t)HID * G4];           // tf32-rounded W [k][n]
static __device__ float g_hbuf[2][BATCH * HID];           // ping-pong hidden (tf32-rounded)
static __device__ unsigned g_bar;                         // grid barrier counter

__global__ void reset_kernel() {
    int i = blockIdx.x * blockDim.x + threadIdx.x;
    if (i == 0) g_bar = 0u;
    if (i < BATCH * HID) g_hbuf[0][i] = 0.0f;
}

__device__ __forceinline__ float sigm(float x) { return 1.0f / (1.0f + __expf(-x)); }

__device__ __forceinline__ void cpa16(uint32_t smem_dst, const void* gsrc) {
    asm volatile("cp.async.cg.shared.global [%0], [%1], 16;" :: "r"(smem_dst), "l"(gsrc));
}
__device__ __forceinline__ void cpa_commit() { asm volatile("cp.async.commit_group;"); }
__device__ __forceinline__ void cpa_wait0()  { asm volatile("cp.async.wait_group 0;" ::: "memory"); }
__device__ __forceinline__ void cpa_wait1()  { asm volatile("cp.async.wait_group 1;" ::: "memory"); }

__device__ __forceinline__ float totf32(float x) {
    unsigned u;
    asm("cvt.rna.tf32.f32 %0, %1;" : "=r"(u) : "f"(x));
    return __uint_as_float(u);
}

// ---------------------------------------------------------------------------
// Pre-pass 1: elementwise tf32 rounding of activations -> g_xa.
// ---------------------------------------------------------------------------
__global__ __launch_bounds__(256) void conv_a_kernel(const float* __restrict__ in) {
    size_t i = (size_t)blockIdx.x * 256 + threadIdx.x;
    float4 v = ((const float4*)in)[i];
    v.x = totf32(v.x); v.y = totf32(v.y); v.z = totf32(v.z); v.w = totf32(v.w);
    ((float4*)g_xa)[i] = v;
}

// ---------------------------------------------------------------------------
// Pre-pass 2: elementwise tf32 rounding of W [k][n] -> g_wr (same layout).
// ---------------------------------------------------------------------------
__global__ __launch_bounds__(256) void conv_w_kernel(const float* __restrict__ W) {
    size_t i = (size_t)blockIdx.x * 256 + threadIdx.x;
    float4 v = ((const float4*)W)[i];
    v.x = totf32(v.x); v.y = totf32(v.y); v.z = totf32(v.z); v.w = totf32(v.w);
    ((float4*)g_wr)[i] = v;
}

// ---------------------------------------------------------------------------
// wmma-tf32 projection (unchanged from the passing round-7 version).
// ---------------------------------------------------------------------------
#define PM 128
#define PN 128
#define PKC 32
#define SA_STR 36
#define SB_STR 132
#define PSTG (PM * SA_STR + PKC * SB_STR)        // 8832 floats
#define EP_STR 132
#define PJ_SMEM_FLOATS (2 * PSTG + PN)
#define PJ_SMEM_BYTES (PJ_SMEM_FLOATS * 4)       // 71168 B

__device__ __forceinline__ void proj_fill(uint32_t stg_u32,
                                          const float* __restrict__ a_r0,
                                          const float* __restrict__ w_c0,
                                          int k0, int tid) {
    uint32_t aB = stg_u32;
    uint32_t bB = stg_u32 + PM * SA_STR * 4;
#pragma unroll
    for (int i = 0; i < 4; i++) {
        int u = tid + 256 * i;
        int r = u >> 3, f = u & 7;
        cpa16(aB + (r * SA_STR + f * 4) * 4, a_r0 + (size_t)r * HID + k0 + f * 4);
    }
#pragma unroll
    for (int i = 0; i < 4; i++) {
        int u = tid + 256 * i;
        int r = u >> 5, f = u & 31;
        cpa16(bB + (r * SB_STR + f * 4) * 4, w_c0 + (size_t)(k0 + r) * G4 + f * 4);
    }
}

__global__ __launch_bounds__(256, 2) void proj_wmma_kernel(const float* __restrict__ bx,
                                                           const float* __restrict__ bh) {
    extern __shared__ float ps[];
    float* sBias = ps + 2 * PSTG;

    const int tid = threadIdx.x;
    const int wid = tid >> 5;
    const int wm  = wid & 3;
    const int wn  = wid >> 2;

    const int col0 = blockIdx.x * PN;
    const int row0 = blockIdx.y * PM;

    const uint32_t ps_u32 = (uint32_t)__cvta_generic_to_shared(ps);
    const float* a_r0 = g_xa + (size_t)row0 * HID;
    const float* w_c0 = g_wr + col0;

    if (tid < PN) sBias[tid] = bx[col0 + tid] + bh[col0 + tid];

    wmma::fragment<wmma::accumulator, 16, 16, 8, float> acc[2][4];
#pragma unroll
    for (int mt = 0; mt < 2; mt++)
#pragma unroll
        for (int nt = 0; nt < 4; nt++) wmma::fill_fragment(acc[mt][nt], 0.0f);

    proj_fill(ps_u32, a_r0, w_c0, 0, tid);
    cpa_commit();
    cpa_wait0();
    __syncthreads();

#pragma unroll 1
    for (int c = 0; c < HID / PKC; c++) {
        const int cs = c & 1, ns = cs ^ 1;
        const float* sA = ps + cs * PSTG;
        const float* sB = sA + PM * SA_STR;

        if (c < HID / PKC - 1) {
            proj_fill(ps_u32 + ns * PSTG * 4, a_r0, w_c0, (c + 1) * PKC, tid);
            cpa_commit();
        }

#pragma unroll
        for (int kt = 0; kt < 4; kt++) {
            wmma::fragment<wmma::matrix_a, 16, 16, 8, wmma::precision::tf32, wmma::row_major> af[2];
            wmma::load_matrix_sync(af[0], sA + (wm * 32 +  0) * SA_STR + kt * 8, SA_STR);
            wmma::load_matrix_sync(af[1], sA + (wm * 32 + 16) * SA_STR + kt * 8, SA_STR);
#pragma unroll
            for (int nt = 0; nt < 4; nt++) {
                wmma::fragment<wmma::matrix_b, 16, 16, 8, wmma::precision::tf32, wmma::row_major> bf;
                wmma::load_matrix_sync(bf, sB + (kt * 8) * SB_STR + wn * 64 + nt * 16, SB_STR);
                wmma::mma_sync(acc[0][nt], af[0], bf, acc[0][nt]);
                wmma::mma_sync(acc[1][nt], af[1], bf, acc[1][nt]);
            }
        }

        cpa_wait0();
        __syncthreads();
    }

    float* sEpi = ps;
#pragma unroll
    for (int mt = 0; mt < 2; mt++)
#pragma unroll
        for (int nt = 0; nt < 4; nt++)
            wmma::store_matrix_sync(sEpi + (wm * 32 + mt * 16) * EP_STR + wn * 64 + nt * 16,
                                    acc[mt][nt], EP_STR, wmma::mem_row_major);
    __syncthreads();

    const int r    = tid >> 1;
    const int half = (tid & 1) * 64;
    const int m = row0 + r;
    const int b = m >> 9;
    const int s = m & (SEQ - 1);
    float* dst = &g_xg[((size_t)s * BATCH + b) * G4 + col0 + half];
#pragma unroll
    for (int j = 0; j < 64; j += 4) {
        float4 v = *(float4*)&sEpi[r * EP_STR + half + j];
        v.x += sBias[half + j + 0];
        v.y += sBias[half + j + 1];
        v.z += sBias[half + j + 2];
        v.w += sBias[half + j + 3];
        *(float4*)&dst[j] = v;
    }
}

// ---------------------------------------------------------------------------
// Persistent recurrence kernel, wmma-tf32 edition.
// 128 CTAs (1/SM). CTA owns j in [j0,j0+8) -> 32 gate cols (local c = g*8+jj).
// sWh [1024][36] tf32-rounded, resident all layer. 8 warps = 4(M)x2(N) grid of
// 16x16 output tiles, each iterating all K -> no reduction. h chunks (64x128)
// double-buffered via cp.async; g_hbuf holds tf32-rounded h (GEMM-only food);
// hs/hT get full fp32 h. Cell state in fp32 registers.
// ---------------------------------------------------------------------------
#define SW2 36
#define SH2 132
#define SG2 36
#define LS_SMEM_FLOATS (HID * SW2 + 2 * 64 * SH2 + 64 * SG2)   // 56064
#define LS_SMEM_BYTES  (LS_SMEM_FLOATS * 4)                    // 224256

__global__ __launch_bounds__(256, 1) void lstm_seq_kernel(const float* __restrict__ Wh,
                                                          float* __restrict__ hs,
                                                          float* __restrict__ hT,
                                                          float* __restrict__ cT) {
    extern __shared__ float sm[];
    float* sWh = sm;                          // [1024][36]  (k-major, 32 local cols)
    float* sH  = sm + HID * SW2;              // 2 x [64][132]
    float* sG  = sH + 2 * 64 * SH2;           // [64][36]

    const int tid = threadIdx.x;
    const int wid = tid >> 5;
    const int j0  = blockIdx.x * 8;

    // Wh slice fill, tf32-rounded (once per layer): local col c -> global g*1024+j0+jj
#pragma unroll 2
    for (int it = 0; it < 128; it++) {
        int idx = it * 256 + tid;
        int c = idx & 31, k = idx >> 5;
        int gcol = ((c >> 3) << 10) + j0 + (c & 7);
        sWh[k * SW2 + c] = totf32(Wh[(size_t)k * G4 + gcol]);
    }

    const int wm = wid & 3;                   // M tile: rows wm*16..+16
    const int wn = wid >> 2;                  // N tile: cols wn*16..+16
    const uint32_t sH_u32 = (uint32_t)__cvta_generic_to_shared(sH);

    float creg[2] = {0.0f, 0.0f};
    __syncthreads();

    unsigned target = NCTA;
    for (int t = 0; t < SEQ; t++) {
        const float* __restrict__ h_in = g_hbuf[t & 1];
        float* __restrict__ h_out      = g_hbuf[(t & 1) ^ 1];
        const float* __restrict__ xg_t = g_xg + (size_t)t * BATCH * G4;

        // prefetch xg operands for the cell update (hidden behind the GEMM)
        float xr[2][4];
#pragma unroll
        for (int q = 0; q < 2; q++) {
            int idx = q * 256 + tid;
            int bb = idx >> 3, jj = idx & 7;
#pragma unroll
            for (int g = 0; g < 4; g++)
                xr[q][g] = __ldg(&xg_t[(size_t)bb * G4 + (g << 10) + j0 + jj]);
        }

        wmma::fragment<wmma::accumulator, 16, 16, 8, float> acc;
        wmma::fill_fragment(acc, 0.0f);

        // prologue: chunk 0 -> buffer 0
        {
            const float* hsrc = h_in;
#pragma unroll
            for (int i = 0; i < 8; i++) {
                int idx = i * 256 + tid;
                int row = idx >> 5;
                int f4  = (idx & 31) * 4;
                cpa16(sH_u32 + (row * SH2 + f4) * 4, hsrc + (size_t)row * HID + f4);
            }
            cpa_commit();
        }

#pragma unroll 1
        for (int ch = 0; ch < 8; ch++) {
            const int cb = ch & 1;
            if (ch < 7) {   // prefetch next chunk into other buffer
                const float* hsrc = h_in + (ch + 1) * 128;
                uint32_t dst = sH_u32 + ((cb ^ 1) * 64 * SH2) * 4;
#pragma unroll
                for (int i = 0; i < 8; i++) {
                    int idx = i * 256 + tid;
                    int row = idx >> 5;
                    int f4  = (idx & 31) * 4;
                    cpa16(dst + (row * SH2 + f4) * 4, hsrc + (size_t)row * HID + f4);
                }
                cpa_commit();
                cpa_wait1();
            } else {
                cpa_wait0();
            }
            __syncthreads();

            const float* sHc = sH + cb * 64 * SH2;
            const float* sWc = sWh + (ch * 128) * SW2;
#pragma unroll
            for (int kt = 0; kt < 16; kt++) {
                wmma::fragment<wmma::matrix_a, 16, 16, 8, wmma::precision::tf32, wmma::row_major> af;
                wmma::fragment<wmma::matrix_b, 16, 16, 8, wmma::precision::tf32, wmma::row_major> bf;
                wmma::load_matrix_sync(af, sHc + (wm * 16) * SH2 + kt * 8, SH2);
                wmma::load_matrix_sync(bf, sWc + (kt * 8) * SW2 + wn * 16, SW2);
                wmma::mma_sync(acc, af, bf, acc);
            }
            __syncthreads();
        }

        // gates to smem (full values, no reduction needed)
        wmma::store_matrix_sync(sG + (wm * 16) * SG2 + wn * 16, acc, SG2, wmma::mem_row_major);
        __syncthreads();

        // cell update: c in fp32 registers; h_out tf32-rounded (GEMM input only)
#pragma unroll
        for (int q = 0; q < 2; q++) {
            int idx = q * 256 + tid;
            int bb = idx >> 3, jj = idx & 7;
            int j  = j0 + jj;
            float gi = sG[bb * SG2 + jj]      + xr[q][0];
            float gf = sG[bb * SG2 + 8 + jj]  + xr[q][1];
            float gg = sG[bb * SG2 + 16 + jj] + xr[q][2];
            float go = sG[bb * SG2 + 24 + jj] + xr[q][3];
            float cn = sigm(gf) * creg[q] + sigm(gi) * tanhf(gg);
            float hn = sigm(go) * tanhf(cn);
            creg[q] = cn;
            h_out[bb * HID + j] = totf32(hn);
            hs[((size_t)bb * SEQ + t) * HID + j] = hn;
            if (t == SEQ - 1) {
                hT[bb * HID + j] = hn;
                cT[bb * HID + j] = cn;
            }
        }

        // device-wide barrier: order all h_out stores before any CTA proceeds
        __threadfence();
        __syncthreads();
        if (tid == 0) {
            atomicAdd(&g_bar, 1u);
            while (*(volatile unsigned*)&g_bar < target) __nanosleep(64);
        }
        __syncthreads();
        target += NCTA;
    }
}

// ---------------------------------------------------------------------------
extern "C" void kernel_launch(void* const* d_in, const int* in_sizes, int n_in,
                              void* d_out, int out_size) {
    (void)in_sizes; (void)n_in; (void)out_size;
    const float* x     = (const float*)d_in[0];
    const float* Wx[2] = {(const float*)d_in[1], (const float*)d_in[5]};
    const float* bx[2] = {(const float*)d_in[2], (const float*)d_in[6]};
    const float* Wh[2] = {(const float*)d_in[3], (const float*)d_in[7]};
    const float* bh[2] = {(const float*)d_in[4], (const float*)d_in[8]};

    float* out = (float*)d_out;
    float* hs  = out;                          // (B,S,H): layer0 scratch, then final layer1 output
    float* hT  = out + OUT_ELEMS;              // (L,B,H)
    float* cT  = hT + 2 * BATCH * HID;         // (L,B,H)

    static int attr_set = 0;
    if (!attr_set) {
        cudaFuncSetAttribute(lstm_seq_kernel, cudaFuncAttributeMaxDynamicSharedMemorySize,
                             LS_SMEM_BYTES);
        cudaFuncSetAttribute(proj_wmma_kernel, cudaFuncAttributeMaxDynamicSharedMemorySize,
                             PJ_SMEM_BYTES);
        attr_set = 1;
    }

    dim3 tgrid(G4 / PN, (BATCH * SEQ) / PM);   // (32, 256)

    for (int l = 0; l < 2; l++) {
        const float* A = (l == 0) ? x : hs;    // layer1 reads layer0's h sequence from d_out
        conv_a_kernel<<<(int)(OUT_ELEMS / 1024), 256>>>(A);
        conv_w_kernel<<<(HID * G4) / 1024, 256>>>(Wx[l]);
        proj_wmma_kernel<<<tgrid, 256, PJ_SMEM_BYTES>>>(bx[l], bh[l]);
        reset_kernel<<<(BATCH * HID + 255) / 256, 256>>>();
        lstm_seq_kernel<<<NCTA, 256, LS_SMEM_BYTES>>>(
            Wh[l], hs, hT + l * BATCH * HID, cT + l * BATCH * HID);
    }
}

// round 9
// speedup vs baseline: 3.0572x; 1.4897x over previous
#include <cuda_runtime.h>
#include <cuda_bf16.h>
#include <mma.h>
#include <cstdint>
#include <cstddef>

using namespace nvcuda;

#define BATCH 64
#define SEQ   512
#define HID   1024
#define G4    4096
#define NCTA  128
#define OUT_ELEMS ((size_t)BATCH * SEQ * HID)

// Scratch (device globals — no allocation allowed).
static __device__ float g_xg[(size_t)SEQ * BATCH * G4];          // [t][b][g]
static __device__ float g_xa[(size_t)BATCH * SEQ * HID];         // tf32-rounded activations
static __device__ float g_wr[(size_t)HID * G4];                  // tf32-rounded W [k][n]
static __device__ __nv_bfloat16 g_hbuf[2][BATCH * HID];          // ping-pong hidden (bf16)
static __device__ unsigned g_bar;                                // grid barrier counter

__global__ void reset_kernel() {
    int i = blockIdx.x * blockDim.x + threadIdx.x;
    if (i == 0) g_bar = 0u;
    if (i < BATCH * HID) g_hbuf[0][i] = __float2bfloat16(0.0f);
}

__device__ __forceinline__ float sigm(float x) { return 1.0f / (1.0f + __expf(-x)); }

__device__ __forceinline__ void cpa16(uint32_t smem_dst, const void* gsrc) {
    asm volatile("cp.async.cg.shared.global [%0], [%1], 16;" :: "r"(smem_dst), "l"(gsrc));
}
__device__ __forceinline__ void cpa_commit() { asm volatile("cp.async.commit_group;"); }
__device__ __forceinline__ void cpa_wait0()  { asm volatile("cp.async.wait_group 0;" ::: "memory"); }
__device__ __forceinline__ void cpa_wait1()  { asm volatile("cp.async.wait_group 1;" ::: "memory"); }

__device__ __forceinline__ float totf32(float x) {
    unsigned u;
    asm("cvt.rna.tf32.f32 %0, %1;" : "=r"(u) : "f"(x));
    return __uint_as_float(u);
}

// ---------------------------------------------------------------------------
// Pre-pass 1: elementwise tf32 rounding of activations -> g_xa.
// ---------------------------------------------------------------------------
__global__ __launch_bounds__(256) void conv_a_kernel(const float* __restrict__ in) {
    size_t i = (size_t)blockIdx.x * 256 + threadIdx.x;
    float4 v = ((const float4*)in)[i];
    v.x = totf32(v.x); v.y = totf32(v.y); v.z = totf32(v.z); v.w = totf32(v.w);
    ((float4*)g_xa)[i] = v;
}

// ---------------------------------------------------------------------------
// Pre-pass 2: elementwise tf32 rounding of W [k][n] -> g_wr (same layout).
// ---------------------------------------------------------------------------
__global__ __launch_bounds__(256) void conv_w_kernel(const float* __restrict__ W) {
    size_t i = (size_t)blockIdx.x * 256 + threadIdx.x;
    float4 v = ((const float4*)W)[i];
    v.x = totf32(v.x); v.y = totf32(v.y); v.z = totf32(v.z); v.w = totf32(v.w);
    ((float4*)g_wr)[i] = v;
}

// ---------------------------------------------------------------------------
// wmma-tf32 projection (unchanged from the passing round-7/8 version).
// ---------------------------------------------------------------------------
#define PM 128
#define PN 128
#define PKC 32
#define SA_STR 36
#define SB_STR 132
#define PSTG (PM * SA_STR + PKC * SB_STR)        // 8832 floats
#define EP_STR 132
#define PJ_SMEM_FLOATS (2 * PSTG + PN)
#define PJ_SMEM_BYTES (PJ_SMEM_FLOATS * 4)       // 71168 B

__device__ __forceinline__ void proj_fill(uint32_t stg_u32,
                                          const float* __restrict__ a_r0,
                                          const float* __restrict__ w_c0,
                                          int k0, int tid) {
    uint32_t aB = stg_u32;
    uint32_t bB = stg_u32 + PM * SA_STR * 4;
#pragma unroll
    for (int i = 0; i < 4; i++) {
        int u = tid + 256 * i;
        int r = u >> 3, f = u & 7;
        cpa16(aB + (r * SA_STR + f * 4) * 4, a_r0 + (size_t)r * HID + k0 + f * 4);
    }
#pragma unroll
    for (int i = 0; i < 4; i++) {
        int u = tid + 256 * i;
        int r = u >> 5, f = u & 31;
        cpa16(bB + (r * SB_STR + f * 4) * 4, w_c0 + (size_t)(k0 + r) * G4 + f * 4);
    }
}

__global__ __launch_bounds__(256, 2) void proj_wmma_kernel(const float* __restrict__ bx,
                                                           const float* __restrict__ bh) {
    extern __shared__ float ps[];
    float* sBias = ps + 2 * PSTG;

    const int tid = threadIdx.x;
    const int wid = tid >> 5;
    const int wm  = wid & 3;
    const int wn  = wid >> 2;

    const int col0 = blockIdx.x * PN;
    const int row0 = blockIdx.y * PM;

    const uint32_t ps_u32 = (uint32_t)__cvta_generic_to_shared(ps);
    const float* a_r0 = g_xa + (size_t)row0 * HID;
    const float* w_c0 = g_wr + col0;

    if (tid < PN) sBias[tid] = bx[col0 + tid] + bh[col0 + tid];

    wmma::fragment<wmma::accumulator, 16, 16, 8, float> acc[2][4];
#pragma unroll
    for (int mt = 0; mt < 2; mt++)
#pragma unroll
        for (int nt = 0; nt < 4; nt++) wmma::fill_fragment(acc[mt][nt], 0.0f);

    proj_fill(ps_u32, a_r0, w_c0, 0, tid);
    cpa_commit();
    cpa_wait0();
    __syncthreads();

#pragma unroll 1
    for (int c = 0; c < HID / PKC; c++) {
        const int cs = c & 1, ns = cs ^ 1;
        const float* sA = ps + cs * PSTG;
        const float* sB = sA + PM * SA_STR;

        if (c < HID / PKC - 1) {
            proj_fill(ps_u32 + ns * PSTG * 4, a_r0, w_c0, (c + 1) * PKC, tid);
            cpa_commit();
        }

#pragma unroll
        for (int kt = 0; kt < 4; kt++) {
            wmma::fragment<wmma::matrix_a, 16, 16, 8, wmma::precision::tf32, wmma::row_major> af[2];
            wmma::load_matrix_sync(af[0], sA + (wm * 32 +  0) * SA_STR + kt * 8, SA_STR);
            wmma::load_matrix_sync(af[1], sA + (wm * 32 + 16) * SA_STR + kt * 8, SA_STR);
#pragma unroll
            for (int nt = 0; nt < 4; nt++) {
                wmma::fragment<wmma::matrix_b, 16, 16, 8, wmma::precision::tf32, wmma::row_major> bf;
                wmma::load_matrix_sync(bf, sB + (kt * 8) * SB_STR + wn * 64 + nt * 16, SB_STR);
                wmma::mma_sync(acc[0][nt], af[0], bf, acc[0][nt]);
                wmma::mma_sync(acc[1][nt], af[1], bf, acc[1][nt]);
            }
        }

        cpa_wait0();
        __syncthreads();
    }

    float* sEpi = ps;
#pragma unroll
    for (int mt = 0; mt < 2; mt++)
#pragma unroll
        for (int nt = 0; nt < 4; nt++)
            wmma::store_matrix_sync(sEpi + (wm * 32 + mt * 16) * EP_STR + wn * 64 + nt * 16,
                                    acc[mt][nt], EP_STR, wmma::mem_row_major);
    __syncthreads();

    const int r    = tid >> 1;
    const int half = (tid & 1) * 64;
    const int m = row0 + r;
    const int b = m >> 9;
    const int s = m & (SEQ - 1);
    float* dst = &g_xg[((size_t)s * BATCH + b) * G4 + col0 + half];
#pragma unroll
    for (int j = 0; j < 64; j += 4) {
        float4 v = *(float4*)&sEpi[r * EP_STR + half + j];
        v.x += sBias[half + j + 0];
        v.y += sBias[half + j + 1];
        v.z += sBias[half + j + 2];
        v.w += sBias[half + j + 3];
        *(float4*)&dst[j] = v;
    }
}

// ---------------------------------------------------------------------------
// Persistent recurrence kernel, bf16 edition.
// 128 CTAs (1/SM). CTA owns j in [j0,j0+8) -> 32 gate cols. sWh [1024][40] bf16
// resident all layer. sH single buffer [64][1032] bf16 = whole h tile; filled in
// 2 k-half commit groups (second half overlapped with first half's MMA).
// 8 warps = 4(M)x2(N) 16x16 tiles, K iterated in full per warp -> no reduction.
// Gates accumulate fp32; cell state fp32 in registers; hs/hT get fp32 h;
// g_hbuf gets bf16 h (GEMM food only). 5 syncthreads/step total.
// ---------------------------------------------------------------------------
#define SWS 40
#define SHS 1032
#define SG2 36
#define LS_WH_BYTES (HID * SWS * 2)                   // 81920
#define LS_H_BYTES  (64 * SHS * 2)                    // 132096
#define LS_SMEM_BYTES (LS_WH_BYTES + LS_H_BYTES + 64 * SG2 * 4)   // 223232

__global__ __launch_bounds__(256, 1) void lstm_seq_kernel(const float* __restrict__ Wh,
                                                          float* __restrict__ hs,
                                                          float* __restrict__ hT,
                                                          float* __restrict__ cT) {
    extern __shared__ char smc[];
    __nv_bfloat16* sWh = (__nv_bfloat16*)smc;                       // [1024][40]
    __nv_bfloat16* sH  = (__nv_bfloat16*)(smc + LS_WH_BYTES);       // [64][1032]
    float*         sG  = (float*)(smc + LS_WH_BYTES + LS_H_BYTES);  // [64][36]

    const int tid = threadIdx.x;
    const int wid = tid >> 5;
    const int j0  = blockIdx.x * 8;

    // Wh slice fill, bf16-rounded (once per layer)
#pragma unroll 2
    for (int it = 0; it < 128; it++) {
        int idx = it * 256 + tid;
        int c = idx & 31, k = idx >> 5;
        int gcol = ((c >> 3) << 10) + j0 + (c & 7);
        sWh[k * SWS + c] = __float2bfloat16_rn(Wh[(size_t)k * G4 + gcol]);
    }

    const int wm = wid & 3;                   // M tile: rows wm*16..+16
    const int wn = wid >> 2;                  // N tile: cols wn*16..+16
    const uint32_t sH_u32 = (uint32_t)__cvta_generic_to_shared(sH);

    float creg[2] = {0.0f, 0.0f};
    __syncthreads();

    unsigned target = NCTA;
    for (int t = 0; t < SEQ; t++) {
        const __nv_bfloat16* __restrict__ h_in = g_hbuf[t & 1];
        __nv_bfloat16* __restrict__ h_out      = g_hbuf[(t & 1) ^ 1];
        const float* __restrict__ xg_t = g_xg + (size_t)t * BATCH * G4;

        // h fill, two k-half commit groups.
        // idx -> row = idx>>6, col16 = idx&63 (+64 for phase 2); 16B granules.
#pragma unroll
        for (int i = 0; i < 16; i++) {
            int idx = i * 256 + tid;
            int row = idx >> 6, c16 = idx & 63;
            cpa16(sH_u32 + row * (SHS * 2) + c16 * 16,
                  (const char*)h_in + (size_t)row * (HID * 2) + c16 * 16);
        }
        cpa_commit();
#pragma unroll
        for (int i = 0; i < 16; i++) {
            int idx = i * 256 + tid;
            int row = idx >> 6, c16 = (idx & 63) + 64;
            cpa16(sH_u32 + row * (SHS * 2) + c16 * 16,
                  (const char*)h_in + (size_t)row * (HID * 2) + c16 * 16);
        }
        cpa_commit();

        // prefetch xg operands for the cell update (hidden behind the GEMM)
        float xr[2][4];
#pragma unroll
        for (int q = 0; q < 2; q++) {
            int idx = q * 256 + tid;
            int bb = idx >> 3, jj = idx & 7;
#pragma unroll
            for (int g = 0; g < 4; g++)
                xr[q][g] = __ldg(&xg_t[(size_t)bb * G4 + (g << 10) + j0 + jj]);
        }

        wmma::fragment<wmma::accumulator, 16, 16, 16, float> acc;
        wmma::fill_fragment(acc, 0.0f);

        cpa_wait1();            // first k-half landed
        __syncthreads();
#pragma unroll
        for (int kt = 0; kt < 32; kt++) {
            wmma::fragment<wmma::matrix_a, 16, 16, 16, __nv_bfloat16, wmma::row_major> af;
            wmma::fragment<wmma::matrix_b, 16, 16, 16, __nv_bfloat16, wmma::row_major> bf;
            wmma::load_matrix_sync(af, sH + (wm * 16) * SHS + kt * 16, SHS);
            wmma::load_matrix_sync(bf, sWh + (kt * 16) * SWS + wn * 16, SWS);
            wmma::mma_sync(acc, af, bf, acc);
        }
        cpa_wait0();            // second k-half landed
        __syncthreads();
#pragma unroll
        for (int kt = 32; kt < 64; kt++) {
            wmma::fragment<wmma::matrix_a, 16, 16, 16, __nv_bfloat16, wmma::row_major> af;
            wmma::fragment<wmma::matrix_b, 16, 16, 16, __nv_bfloat16, wmma::row_major> bf;
            wmma::load_matrix_sync(af, sH + (wm * 16) * SHS + kt * 16, SHS);
            wmma::load_matrix_sync(bf, sWh + (kt * 16) * SWS + wn * 16, SWS);
            wmma::mma_sync(acc, af, bf, acc);
        }

        // gates to smem (full values, no reduction needed)
        wmma::store_matrix_sync(sG + (wm * 16) * SG2 + wn * 16, acc, SG2, wmma::mem_row_major);
        __syncthreads();

        // cell update: c in fp32 regs; h_out bf16 (GEMM input only); hs/hT fp32
#pragma unroll
        for (int q = 0; q < 2; q++) {
            int idx = q * 256 + tid;
            int bb = idx >> 3, jj = idx & 7;
            int j  = j0 + jj;
            float gi = sG[bb * SG2 + jj]      + xr[q][0];
            float gf = sG[bb * SG2 + 8 + jj]  + xr[q][1];
            float gg = sG[bb * SG2 + 16 + jj] + xr[q][2];
            float go = sG[bb * SG2 + 24 + jj] + xr[q][3];
            float cn = sigm(gf) * creg[q] + sigm(gi) * tanhf(gg);
            float hn = sigm(go) * tanhf(cn);
            creg[q] = cn;
            h_out[bb * HID + j] = __float2bfloat16_rn(hn);
            hs[((size_t)bb * SEQ + t) * HID + j] = hn;
            if (t == SEQ - 1) {
                hT[bb * HID + j] = hn;
                cT[bb * HID + j] = cn;
            }
        }

        // device-wide barrier: order all h_out stores before any CTA proceeds
        __threadfence();
        __syncthreads();
        if (tid == 0) {
            atomicAdd(&g_bar, 1u);
            while (*(volatile unsigned*)&g_bar < target) __nanosleep(32);
        }
        __syncthreads();
        target += NCTA;
    }
}

// ---------------------------------------------------------------------------
extern "C" void kernel_launch(void* const* d_in, const int* in_sizes, int n_in,
                              void* d_out, int out_size) {
    (void)in_sizes; (void)n_in; (void)out_size;
    const float* x     = (const float*)d_in[0];
    const float* Wx[2] = {(const float*)d_in[1], (const float*)d_in[5]};
    const float* bx[2] = {(const float*)d_in[2], (const float*)d_in[6]};
    const float* Wh[2] = {(const float*)d_in[3], (const float*)d_in[7]};
    const float* bh[2] = {(const float*)d_in[4], (const float*)d_in[8]};

    float* out = (float*)d_out;
    float* hs  = out;                          // (B,S,H): layer0 scratch, then final layer1 output
    float* hT  = out + OUT_ELEMS;              // (L,B,H)
    float* cT  = hT + 2 * BATCH * HID;         // (L,B,H)

    static int attr_set = 0;
    if (!attr_set) {
        cudaFuncSetAttribute(lstm_seq_kernel, cudaFuncAttributeMaxDynamicSharedMemorySize,
                             LS_SMEM_BYTES);
        cudaFuncSetAttribute(proj_wmma_kernel, cudaFuncAttributeMaxDynamicSharedMemorySize,
                             PJ_SMEM_BYTES);
        attr_set = 1;
    }

    dim3 tgrid(G4 / PN, (BATCH * SEQ) / PM);   // (32, 256)

    for (int l = 0; l < 2; l++) {
        const float* A = (l == 0) ? x : hs;    // layer1 reads layer0's h sequence from d_out
        conv_a_kernel<<<(int)(OUT_ELEMS / 1024), 256>>>(A);
        conv_w_kernel<<<(HID * G4) / 1024, 256>>>(Wx[l]);
        proj_wmma_kernel<<<tgrid, 256, PJ_SMEM_BYTES>>>(bx[l], bh[l]);
        reset_kernel<<<(BATCH * HID + 255) / 256, 256>>>();
        lstm_seq_kernel<<<NCTA, 256, LS_SMEM_BYTES>>>(
            Wh[l], hs, hT + l * BATCH * HID, cT + l * BATCH * HID);
    }
}

// round 11
// speedup vs baseline: 3.1925x; 1.0443x over previous
#include <cuda_runtime.h>
#include <cuda_bf16.h>
#include <mma.h>
#include <cstdint>
#include <cstddef>

using namespace nvcuda;

#define BATCH 64
#define SEQ   512
#define HID   1024
#define G4    4096
#define NCTA  128
#define OUT_ELEMS ((size_t)BATCH * SEQ * HID)

// Scratch (device globals — no allocation allowed).
static __device__ float g_xg[(size_t)SEQ * BATCH * G4];          // [t][b][g]
static __device__ float g_xa[(size_t)BATCH * SEQ * HID];         // tf32-rounded activations
static __device__ float g_wr[(size_t)HID * G4];                  // tf32-rounded W [k][n]
static __device__ __nv_bfloat16 g_hbuf[2][BATCH * HID];          // ping-pong hidden (bf16)
static __device__ unsigned g_bar;                                // grid barrier counter

__global__ void reset_kernel() {
    int i = blockIdx.x * blockDim.x + threadIdx.x;
    if (i == 0) g_bar = 0u;
    if (i < BATCH * HID) g_hbuf[0][i] = __float2bfloat16(0.0f);
}

__device__ __forceinline__ float sigm(float x) { return 1.0f / (1.0f + __expf(-x)); }

__device__ __forceinline__ void cpa16(uint32_t smem_dst, const void* gsrc) {
    asm volatile("cp.async.cg.shared.global [%0], [%1], 16;" :: "r"(smem_dst), "l"(gsrc));
}
__device__ __forceinline__ void cpa_commit() { asm volatile("cp.async.commit_group;"); }
__device__ __forceinline__ void cpa_wait0()  { asm volatile("cp.async.wait_group 0;" ::: "memory"); }

__device__ __forceinline__ float totf32(float x) {
    unsigned u;
    asm("cvt.rna.tf32.f32 %0, %1;" : "=r"(u) : "f"(x));
    return __uint_as_float(u);
}

// ---------------------------------------------------------------------------
// Pre-pass 1: elementwise tf32 rounding of activations -> g_xa.
// ---------------------------------------------------------------------------
__global__ __launch_bounds__(256) void conv_a_kernel(const float* __restrict__ in) {
    size_t i = (size_t)blockIdx.x * 256 + threadIdx.x;
    float4 v = ((const float4*)in)[i];
    v.x = totf32(v.x); v.y = totf32(v.y); v.z = totf32(v.z); v.w = totf32(v.w);
    ((float4*)g_xa)[i] = v;
}

// ---------------------------------------------------------------------------
// Pre-pass 2: elementwise tf32 rounding of W [k][n] -> g_wr (same layout).
// ---------------------------------------------------------------------------
__global__ __launch_bounds__(256) void conv_w_kernel(const float* __restrict__ W) {
    size_t i = (size_t)blockIdx.x * 256 + threadIdx.x;
    float4 v = ((const float4*)W)[i];
    v.x = totf32(v.x); v.y = totf32(v.y); v.z = totf32(v.z); v.w = totf32(v.w);
    ((float4*)g_wr)[i] = v;
}

// ---------------------------------------------------------------------------
// wmma-tf32 projection (unchanged from the passing round-7/8/9 version).
// ---------------------------------------------------------------------------
#define PM 128
#define PN 128
#define PKC 32
#define SA_STR 36
#define SB_STR 132
#define PSTG (PM * SA_STR + PKC * SB_STR)        // 8832 floats
#define EP_STR 132
#define PJ_SMEM_FLOATS (2 * PSTG + PN)
#define PJ_SMEM_BYTES (PJ_SMEM_FLOATS * 4)       // 71168 B

__device__ __forceinline__ void proj_fill(uint32_t stg_u32,
                                          const float* __restrict__ a_r0,
                                          const float* __restrict__ w_c0,
                                          int k0, int tid) {
    uint32_t aB = stg_u32;
    uint32_t bB = stg_u32 + PM * SA_STR * 4;
#pragma unroll
    for (int i = 0; i < 4; i++) {
        int u = tid + 256 * i;
        int r = u >> 3, f = u & 7;
        cpa16(aB + (r * SA_STR + f * 4) * 4, a_r0 + (size_t)r * HID + k0 + f * 4);
    }
#pragma unroll
    for (int i = 0; i < 4; i++) {
        int u = tid + 256 * i;
        int r = u >> 5, f = u & 31;
        cpa16(bB + (r * SB_STR + f * 4) * 4, w_c0 + (size_t)(k0 + r) * G4 + f * 4);
    }
}

__global__ __launch_bounds__(256, 2) void proj_wmma_kernel(const float* __restrict__ bx,
                                                           const float* __restrict__ bh) {
    extern __shared__ float ps[];
    float* sBias = ps + 2 * PSTG;

    const int tid = threadIdx.x;
    const int wid = tid >> 5;
    const int wm  = wid & 3;
    const int wn  = wid >> 2;

    const int col0 = blockIdx.x * PN;
    const int row0 = blockIdx.y * PM;

    const uint32_t ps_u32 = (uint32_t)__cvta_generic_to_shared(ps);
    const float* a_r0 = g_xa + (size_t)row0 * HID;
    const float* w_c0 = g_wr + col0;

    if (tid < PN) sBias[tid] = bx[col0 + tid] + bh[col0 + tid];

    wmma::fragment<wmma::accumulator, 16, 16, 8, float> acc[2][4];
#pragma unroll
    for (int mt = 0; mt < 2; mt++)
#pragma unroll
        for (int nt = 0; nt < 4; nt++) wmma::fill_fragment(acc[mt][nt], 0.0f);

    proj_fill(ps_u32, a_r0, w_c0, 0, tid);
    cpa_commit();
    cpa_wait0();
    __syncthreads();

#pragma unroll 1
    for (int c = 0; c < HID / PKC; c++) {
        const int cs = c & 1, ns = cs ^ 1;
        const float* sA = ps + cs * PSTG;
        const float* sB = sA + PM * SA_STR;

        if (c < HID / PKC - 1) {
            proj_fill(ps_u32 + ns * PSTG * 4, a_r0, w_c0, (c + 1) * PKC, tid);
            cpa_commit();
        }

#pragma unroll
        for (int kt = 0; kt < 4; kt++) {
            wmma::fragment<wmma::matrix_a, 16, 16, 8, wmma::precision::tf32, wmma::row_major> af[2];
            wmma::load_matrix_sync(af[0], sA + (wm * 32 +  0) * SA_STR + kt * 8, SA_STR);
            wmma::load_matrix_sync(af[1], sA + (wm * 32 + 16) * SA_STR + kt * 8, SA_STR);
#pragma unroll
            for (int nt = 0; nt < 4; nt++) {
                wmma::fragment<wmma::matrix_b, 16, 16, 8, wmma::precision::tf32, wmma::row_major> bf;
                wmma::load_matrix_sync(bf, sB + (kt * 8) * SB_STR + wn * 64 + nt * 16, SB_STR);
                wmma::mma_sync(acc[0][nt], af[0], bf, acc[0][nt]);
                wmma::mma_sync(acc[1][nt], af[1], bf, acc[1][nt]);
            }
        }

        cpa_wait0();
        __syncthreads();
    }

    float* sEpi = ps;
#pragma unroll
    for (int mt = 0; mt < 2; mt++)
#pragma unroll
        for (int nt = 0; nt < 4; nt++)
            wmma::store_matrix_sync(sEpi + (wm * 32 + mt * 16) * EP_STR + wn * 64 + nt * 16,
                                    acc[mt][nt], EP_STR, wmma::mem_row_major);
    __syncthreads();

    const int r    = tid >> 1;
    const int half = (tid & 1) * 64;
    const int m = row0 + r;
    const int b = m >> 9;
    const int s = m & (SEQ - 1);
    float* dst = &g_xg[((size_t)s * BATCH + b) * G4 + col0 + half];
#pragma unroll
    for (int j = 0; j < 64; j += 4) {
        float4 v = *(float4*)&sEpi[r * EP_STR + half + j];
        v.x += sBias[half + j + 0];
        v.y += sBias[half + j + 1];
        v.z += sBias[half + j + 2];
        v.w += sBias[half + j + 3];
        *(float4*)&dst[j] = v;
    }
}

// ---------------------------------------------------------------------------
// Persistent recurrence kernel, bf16, quarter-pipelined.
// 128 CTAs (1/SM). CTA owns j in [j0,j0+8) -> 32 gate cols. sWh [1024][40] bf16
// resident all layer. sH single buffer [64][1032] bf16; filled in 4 k-quarter
// commit groups, MMA starts after the first quarter lands (wait_group 3..0).
// 8 warps = 4(M)x2(N) 16x16 tiles; DUAL accumulator chains (even/odd kt) to
// break the serial HMMA dependency. Gates fp32; c fp32 regs; hs/hT fp32 h;
// g_hbuf bf16 h (GEMM food only). Grid barrier: hard spin with bounded backoff.
// ---------------------------------------------------------------------------
#define SWS 40
#define SHS 1032
#define SG2 36
#define LS_WH_BYTES (HID * SWS * 2)                   // 81920
#define LS_H_BYTES  (64 * SHS * 2)                    // 132096
#define LS_SMEM_BYTES (LS_WH_BYTES + LS_H_BYTES + 64 * SG2 * 4)   // 223232

// one k-quarter of MMA work: kt in [q*16, q*16+16), alternating acc chains
#define STEP_MMA_QUARTER(q)                                                          \
    do {                                                                             \
        _Pragma("unroll")                                                            \
        for (int kt = (q) * 16; kt < (q) * 16 + 16; kt++) {                          \
            wmma::fragment<wmma::matrix_a, 16, 16, 16, __nv_bfloat16, wmma::row_major> af; \
            wmma::fragment<wmma::matrix_b, 16, 16, 16, __nv_bfloat16, wmma::row_major> bf; \
            wmma::load_matrix_sync(af, sH + (wm * 16) * SHS + kt * 16, SHS);         \
            wmma::load_matrix_sync(bf, sWh + (kt * 16) * SWS + wn * 16, SWS);        \
            wmma::mma_sync(accq[kt & 1], af, bf, accq[kt & 1]);                      \
        }                                                                            \
    } while (0)

__global__ __launch_bounds__(256, 1) void lstm_seq_kernel(const float* __restrict__ Wh,
                                                          float* __restrict__ hs,
                                                          float* __restrict__ hT,
                                                          float* __restrict__ cT) {
    extern __shared__ char smc[];
    __nv_bfloat16* sWh = (__nv_bfloat16*)smc;                       // [1024][40]
    __nv_bfloat16* sH  = (__nv_bfloat16*)(smc + LS_WH_BYTES);       // [64][1032]
    float*         sG  = (float*)(smc + LS_WH_BYTES + LS_H_BYTES);  // [64][36]

    const int tid = threadIdx.x;
    const int wid = tid >> 5;
    const int j0  = blockIdx.x * 8;

    // Wh slice fill, bf16-rounded (once per layer)
#pragma unroll 2
    for (int it = 0; it < 128; it++) {
        int idx = it * 256 + tid;
        int c = idx & 31, k = idx >> 5;
        int gcol = ((c >> 3) << 10) + j0 + (c & 7);
        sWh[k * SWS + c] = __float2bfloat16_rn(Wh[(size_t)k * G4 + gcol]);
    }

    const int wm = wid & 3;                   // M tile: rows wm*16..+16
    const int wn = wid >> 2;                  // N tile: cols wn*16..+16
    const uint32_t sH_u32 = (uint32_t)__cvta_generic_to_shared(sH);

    float creg[2] = {0.0f, 0.0f};
    __syncthreads();

    unsigned target = NCTA;
    for (int t = 0; t < SEQ; t++) {
        const __nv_bfloat16* __restrict__ h_in = g_hbuf[t & 1];
        __nv_bfloat16* __restrict__ h_out      = g_hbuf[(t & 1) ^ 1];
        const float* __restrict__ xg_t = g_xg + (size_t)t * BATCH * G4;

        // h fill: 4 k-quarter commit groups (row = 64 x 2048B; 128 16B-granules/row)
#pragma unroll
        for (int qf = 0; qf < 4; qf++) {
#pragma unroll
            for (int i = 0; i < 8; i++) {
                int idx = i * 256 + tid;                 // 0..2047
                int row = idx >> 5;
                int g16 = (idx & 31) + qf * 32;
                cpa16(sH_u32 + row * (SHS * 2) + g16 * 16,
                      (const char*)h_in + (size_t)row * (HID * 2) + g16 * 16);
            }
            cpa_commit();
        }

        // prefetch xg operands for the cell update (overlaps the fill + GEMM)
        float xr[2][4];
#pragma unroll
        for (int q = 0; q < 2; q++) {
            int idx = q * 256 + tid;
            int bb = idx >> 3, jj = idx & 7;
#pragma unroll
            for (int g = 0; g < 4; g++)
                xr[q][g] = __ldg(&xg_t[(size_t)bb * G4 + (g << 10) + j0 + jj]);
        }

        wmma::fragment<wmma::accumulator, 16, 16, 16, float> accq[2];
        wmma::fill_fragment(accq[0], 0.0f);
        wmma::fill_fragment(accq[1], 0.0f);

        // progressive quarter pipeline
        asm volatile("cp.async.wait_group 3;" ::: "memory");
        __syncthreads();
        STEP_MMA_QUARTER(0);
        asm volatile("cp.async.wait_group 2;" ::: "memory");
        __syncthreads();
        STEP_MMA_QUARTER(1);
        asm volatile("cp.async.wait_group 1;" ::: "memory");
        __syncthreads();
        STEP_MMA_QUARTER(2);
        asm volatile("cp.async.wait_group 0;" ::: "memory");
        __syncthreads();
        STEP_MMA_QUARTER(3);

        // combine dual chains, gates to smem
#pragma unroll
        for (int e = 0; e < accq[0].num_elements; e++)
            accq[0].x[e] += accq[1].x[e];
        wmma::store_matrix_sync(sG + (wm * 16) * SG2 + wn * 16, accq[0], SG2, wmma::mem_row_major);
        __syncthreads();

        // cell update: c in fp32 regs; h_out bf16 (GEMM input only); hs/hT fp32
#pragma unroll
        for (int q = 0; q < 2; q++) {
            int idx = q * 256 + tid;
            int bb = idx >> 3, jj = idx & 7;
            int j  = j0 + jj;
            float gi = sG[bb * SG2 + jj]      + xr[q][0];
            float gf = sG[bb * SG2 + 8 + jj]  + xr[q][1];
            float gg = sG[bb * SG2 + 16 + jj] + xr[q][2];
            float go = sG[bb * SG2 + 24 + jj] + xr[q][3];
            float cn = sigm(gf) * creg[q] + sigm(gi) * tanhf(gg);
            float hn = sigm(go) * tanhf(cn);
            creg[q] = cn;
            h_out[bb * HID + j] = __float2bfloat16_rn(hn);
            hs[((size_t)bb * SEQ + t) * HID + j] = hn;
            if (t == SEQ - 1) {
                hT[bb * HID + j] = hn;
                cT[bb * HID + j] = cn;
            }
        }

        // device-wide barrier: order all h_out stores before any CTA proceeds.
        // Fast path: hard poll (no nanosleep wake latency). Bounded backoff
        // after 8192 polls so a pathologically delayed CTA can't livelock us.
        __threadfence();
        __syncthreads();
        if (tid == 0) {
            atomicAdd(&g_bar, 1u);
            int spins = 0;
            while (*(volatile unsigned*)&g_bar < target) {
                if (++spins > 8192) __nanosleep(64);
            }
        }
        __syncthreads();
        target += NCTA;
    }
}

// ---------------------------------------------------------------------------
extern "C" void kernel_launch(void* const* d_in, const int* in_sizes, int n_in,
                              void* d_out, int out_size) {
    (void)in_sizes; (void)n_in; (void)out_size;
    const float* x     = (const float*)d_in[0];
    const float* Wx[2] = {(const float*)d_in[1], (const float*)d_in[5]};
    const float* bx[2] = {(const float*)d_in[2], (const float*)d_in[6]};
    const float* Wh[2] = {(const float*)d_in[3], (const float*)d_in[7]};
    const float* bh[2] = {(const float*)d_in[4], (const float*)d_in[8]};

    float* out = (float*)d_out;
    float* hs  = out;                          // (B,S,H): layer0 scratch, then final layer1 output
    float* hT  = out + OUT_ELEMS;              // (L,B,H)
    float* cT  = hT + 2 * BATCH * HID;         // (L,B,H)

    static int attr_set = 0;
    if (!attr_set) {
        cudaFuncSetAttribute(lstm_seq_kernel, cudaFuncAttributeMaxDynamicSharedMemorySize,
                             LS_SMEM_BYTES);
        cudaFuncSetAttribute(proj_wmma_kernel, cudaFuncAttributeMaxDynamicSharedMemorySize,
                             PJ_SMEM_BYTES);
        attr_set = 1;
    }

    dim3 tgrid(G4 / PN, (BATCH * SEQ) / PM);   // (32, 256)

    for (int l = 0; l < 2; l++) {
        const float* A = (l == 0) ? x : hs;    // layer1 reads layer0's h sequence from d_out
        conv_a_kernel<<<(int)(OUT_ELEMS / 1024), 256>>>(A);
        conv_w_kernel<<<(HID * G4) / 1024, 256>>>(Wx[l]);
        proj_wmma_kernel<<<tgrid, 256, PJ_SMEM_BYTES>>>(bx[l], bh[l]);
        reset_kernel<<<(BATCH * HID + 255) / 256, 256>>>();
        lstm_seq_kernel<<<NCTA, 256, LS_SMEM_BYTES>>>(
            Wh[l], hs, hT + l * BATCH * HID, cT + l * BATCH * HID);
    }
}

// round 12
// speedup vs baseline: 3.4588x; 1.0834x over previous
#include <cuda_runtime.h>
#include <cuda_bf16.h>
#include <mma.h>
#include <cstdint>
#include <cstddef>

using namespace nvcuda;

#define BATCH 64
#define SEQ   512
#define HID   1024
#define G4    4096
#define NCTA  128
#define OUT_ELEMS ((size_t)BATCH * SEQ * HID)

// Scratch (device globals — no allocation allowed).
static __device__ float g_xg[(size_t)SEQ * BATCH * G4];          // [t][b][g]
static __device__ float g_xa[(size_t)BATCH * SEQ * HID];         // tf32-rounded activations
static __device__ float g_wr[(size_t)HID * G4];                  // tf32-rounded W [k][n]
static __device__ __nv_bfloat16 g_hbuf[2][BATCH * HID];          // ping-pong hidden (bf16)
static __device__ unsigned g_bar;                                // grid barrier counter

__device__ __forceinline__ float sigm(float x) { return 1.0f / (1.0f + __expf(-x)); }

__device__ __forceinline__ void cpa16(uint32_t smem_dst, const void* gsrc) {
    asm volatile("cp.async.cg.shared.global [%0], [%1], 16;" :: "r"(smem_dst), "l"(gsrc));
}
__device__ __forceinline__ void cpa_commit() { asm volatile("cp.async.commit_group;"); }
__device__ __forceinline__ void cpa_wait0()  { asm volatile("cp.async.wait_group 0;" ::: "memory"); }

__device__ __forceinline__ float totf32(float x) {
    unsigned u;
    asm("cvt.rna.tf32.f32 %0, %1;" : "=r"(u) : "f"(x));
    return __uint_as_float(u);
}

// ---------------------------------------------------------------------------
// Pre-pass 1: elementwise tf32 rounding of activations -> g_xa (layer 0 only;
// layer 1's g_xa is written directly by the step kernel).
// ---------------------------------------------------------------------------
__global__ __launch_bounds__(256) void conv_a_kernel(const float* __restrict__ in) {
    size_t i = (size_t)blockIdx.x * 256 + threadIdx.x;
    float4 v = ((const float4*)in)[i];
    v.x = totf32(v.x); v.y = totf32(v.y); v.z = totf32(v.z); v.w = totf32(v.w);
    ((float4*)g_xa)[i] = v;
}

// ---------------------------------------------------------------------------
// Pre-pass 2: tf32 rounding of W [k][n] -> g_wr, PLUS per-layer state reset
// (g_bar and g_hbuf[0]) folded in — runs before every lstm launch.
// ---------------------------------------------------------------------------
__global__ __launch_bounds__(256) void conv_w_kernel(const float* __restrict__ W) {
    size_t i = (size_t)blockIdx.x * 256 + threadIdx.x;
    float4 v = ((const float4*)W)[i];
    v.x = totf32(v.x); v.y = totf32(v.y); v.z = totf32(v.z); v.w = totf32(v.w);
    ((float4*)g_wr)[i] = v;
    if (i == 0) g_bar = 0u;
    if (i < (BATCH * HID) / 2) ((uint32_t*)g_hbuf[0])[i] = 0u;   // 2 bf16 zeros
}

// ---------------------------------------------------------------------------
// wmma-tf32 projection (unchanged from the passing round-7..11 version).
// ---------------------------------------------------------------------------
#define PM 128
#define PN 128
#define PKC 32
#define SA_STR 36
#define SB_STR 132
#define PSTG (PM * SA_STR + PKC * SB_STR)        // 8832 floats
#define EP_STR 132
#define PJ_SMEM_FLOATS (2 * PSTG + PN)
#define PJ_SMEM_BYTES (PJ_SMEM_FLOATS * 4)       // 71168 B

__device__ __forceinline__ void proj_fill(uint32_t stg_u32,
                                          const float* __restrict__ a_r0,
                                          const float* __restrict__ w_c0,
                                          int k0, int tid) {
    uint32_t aB = stg_u32;
    uint32_t bB = stg_u32 + PM * SA_STR * 4;
#pragma unroll
    for (int i = 0; i < 4; i++) {
        int u = tid + 256 * i;
        int r = u >> 3, f = u & 7;
        cpa16(aB + (r * SA_STR + f * 4) * 4, a_r0 + (size_t)r * HID + k0 + f * 4);
    }
#pragma unroll
    for (int i = 0; i < 4; i++) {
        int u = tid + 256 * i;
        int r = u >> 5, f = u & 31;
        cpa16(bB + (r * SB_STR + f * 4) * 4, w_c0 + (size_t)(k0 + r) * G4 + f * 4);
    }
}

__global__ __launch_bounds__(256, 2) void proj_wmma_kernel(const float* __restrict__ bx,
                                                           const float* __restrict__ bh) {
    extern __shared__ float ps[];
    float* sBias = ps + 2 * PSTG;

    const int tid = threadIdx.x;
    const int wid = tid >> 5;
    const int wm  = wid & 3;
    const int wn  = wid >> 2;

    const int col0 = blockIdx.x * PN;
    const int row0 = blockIdx.y * PM;

    const uint32_t ps_u32 = (uint32_t)__cvta_generic_to_shared(ps);
    const float* a_r0 = g_xa + (size_t)row0 * HID;
    const float* w_c0 = g_wr + col0;

    if (tid < PN) sBias[tid] = bx[col0 + tid] + bh[col0 + tid];

    wmma::fragment<wmma::accumulator, 16, 16, 8, float> acc[2][4];
#pragma unroll
    for (int mt = 0; mt < 2; mt++)
#pragma unroll
        for (int nt = 0; nt < 4; nt++) wmma::fill_fragment(acc[mt][nt], 0.0f);

    proj_fill(ps_u32, a_r0, w_c0, 0, tid);
    cpa_commit();
    cpa_wait0();
    __syncthreads();

#pragma unroll 1
    for (int c = 0; c < HID / PKC; c++) {
        const int cs = c & 1, ns = cs ^ 1;
        const float* sA = ps + cs * PSTG;
        const float* sB = sA + PM * SA_STR;

        if (c < HID / PKC - 1) {
            proj_fill(ps_u32 + ns * PSTG * 4, a_r0, w_c0, (c + 1) * PKC, tid);
            cpa_commit();
        }

#pragma unroll
        for (int kt = 0; kt < 4; kt++) {
            wmma::fragment<wmma::matrix_a, 16, 16, 8, wmma::precision::tf32, wmma::row_major> af[2];
            wmma::load_matrix_sync(af[0], sA + (wm * 32 +  0) * SA_STR + kt * 8, SA_STR);
            wmma::load_matrix_sync(af[1], sA + (wm * 32 + 16) * SA_STR + kt * 8, SA_STR);
#pragma unroll
            for (int nt = 0; nt < 4; nt++) {
                wmma::fragment<wmma::matrix_b, 16, 16, 8, wmma::precision::tf32, wmma::row_major> bf;
                wmma::load_matrix_sync(bf, sB + (kt * 8) * SB_STR + wn * 64 + nt * 16, SB_STR);
                wmma::mma_sync(acc[0][nt], af[0], bf, acc[0][nt]);
                wmma::mma_sync(acc[1][nt], af[1], bf, acc[1][nt]);
            }
        }

        cpa_wait0();
        __syncthreads();
    }

    float* sEpi = ps;
#pragma unroll
    for (int mt = 0; mt < 2; mt++)
#pragma unroll
        for (int nt = 0; nt < 4; nt++)
            wmma::store_matrix_sync(sEpi + (wm * 32 + mt * 16) * EP_STR + wn * 64 + nt * 16,
                                    acc[mt][nt], EP_STR, wmma::mem_row_major);
    __syncthreads();

    const int r    = tid >> 1;
    const int half = (tid & 1) * 64;
    const int m = row0 + r;
    const int b = m >> 9;
    const int s = m & (SEQ - 1);
    float* dst = &g_xg[((size_t)s * BATCH + b) * G4 + col0 + half];
#pragma unroll
    for (int j = 0; j < 64; j += 4) {
        float4 v = *(float4*)&sEpi[r * EP_STR + half + j];
        v.x += sBias[half + j + 0];
        v.y += sBias[half + j + 1];
        v.z += sBias[half + j + 2];
        v.w += sBias[half + j + 3];
        *(float4*)&dst[j] = v;
    }
}

// ---------------------------------------------------------------------------
// Persistent recurrence kernel: warp-private K-split edition.
// 128 CTAs (1/SM). CTA owns j in [j0,j0+8) -> 32 gate cols. sWh [1024][40] bf16
// resident all layer. 8 warps = 4 K-groups x 2 M-halves; warp tile 32x32 =
// 2x2 fragments (reuse 2x, 4 independent HMMA chains). Each warp cp.async-fills
// ONLY the sH region it reads (its 32 rows x its 256-k quarter, 4 sub-commits),
// so the fill+MMA region needs NO __syncthreads — per-warp wait_group only.
// K-partials staged fp32 in an overlay on sH (dead after MMA reads). Gates
// fp32; c fp32 regs; hs/hT fp32 h; g_hbuf bf16 h; g_xa tf32 h (feeds layer-2
// projection directly — no conv_a pass for layer 2).
// ---------------------------------------------------------------------------
#define SWS 40
#define SHS 1032
#define SGP 36
#define LS_WH_BYTES (HID * SWS * 2)                   // 81920
#define LS_H_BYTES  (64 * SHS * 2)                    // 132096
#define LS_SMEM_BYTES (LS_WH_BYTES + LS_H_BYTES)      // 214016

// one k-sub-quarter: wait own fills (immediate N), then 4 kt of 2x2 mma
#define STEP_SUBQ(sq, waitn)                                                         \
    do {                                                                             \
        asm volatile("cp.async.wait_group " #waitn ";" ::: "memory");                \
        __syncwarp();                                                                \
        _Pragma("unroll")                                                            \
        for (int j = 0; j < 4; j++) {                                                \
            const int k16 = kgrp * 16 + (sq) * 4 + j;                                \
            wmma::fragment<wmma::matrix_a, 16, 16, 16, __nv_bfloat16, wmma::row_major> a0, a1; \
            wmma::fragment<wmma::matrix_b, 16, 16, 16, __nv_bfloat16, wmma::row_major> b0, b1; \
            wmma::load_matrix_sync(a0, sH + (mhalf +  0) * SHS + k16 * 16, SHS);     \
            wmma::load_matrix_sync(a1, sH + (mhalf + 16) * SHS + k16 * 16, SHS);     \
            wmma::load_matrix_sync(b0, sWh + (k16 * 16) * SWS +  0, SWS);            \
            wmma::load_matrix_sync(b1, sWh + (k16 * 16) * SWS + 16, SWS);            \
            wmma::mma_sync(acc[0][0], a0, b0, acc[0][0]);                            \
            wmma::mma_sync(acc[0][1], a0, b1, acc[0][1]);                            \
            wmma::mma_sync(acc[1][0], a1, b0, acc[1][0]);                            \
            wmma::mma_sync(acc[1][1], a1, b1, acc[1][1]);                            \
        }                                                                            \
    } while (0)

__global__ __launch_bounds__(256, 1) void lstm_seq_kernel(const float* __restrict__ Wh,
                                                          float* __restrict__ hs,
                                                          float* __restrict__ hT,
                                                          float* __restrict__ cT) {
    extern __shared__ char smc[];
    __nv_bfloat16* sWh = (__nv_bfloat16*)smc;                       // [1024][40]
    __nv_bfloat16* sH  = (__nv_bfloat16*)(smc + LS_WH_BYTES);       // [64][1032]
    float*         sGp = (float*)(smc + LS_WH_BYTES);               // overlay: [4][64][36]

    const int tid  = threadIdx.x;
    const int wid  = tid >> 5;
    const int lane = tid & 31;
    const int j0   = blockIdx.x * 8;

    // Wh slice fill, bf16-rounded (once per layer)
#pragma unroll 2
    for (int it = 0; it < 128; it++) {
        int idx = it * 256 + tid;
        int c = idx & 31, k = idx >> 5;
        int gcol = ((c >> 3) << 10) + j0 + (c & 7);
        sWh[k * SWS + c] = __float2bfloat16_rn(Wh[(size_t)k * G4 + gcol]);
    }

    const int kgrp  = wid >> 1;               // k-quarter this warp owns
    const int mhalf = (wid & 1) * 32;         // M rows this warp owns
    const uint32_t sH_u32 = (uint32_t)__cvta_generic_to_shared(sH);

    float creg[2] = {0.0f, 0.0f};
    __syncthreads();

    unsigned target = NCTA;
    for (int t = 0; t < SEQ; t++) {
        const __nv_bfloat16* __restrict__ h_in = g_hbuf[t & 1];
        __nv_bfloat16* __restrict__ h_out      = g_hbuf[(t & 1) ^ 1];
        const float* __restrict__ xg_t = g_xg + (size_t)t * BATCH * G4;

        // warp-private fill: 32 rows x 256 k, as 4 sub-commits of 64 k each
#pragma unroll
        for (int sq = 0; sq < 4; sq++) {
#pragma unroll
            for (int i = 0; i < 8; i++) {
                int idx = i * 32 + lane;                  // 0..255
                int row = mhalf + (idx >> 3);
                int bcol = kgrp * 512 + sq * 128 + (idx & 7) * 16;
                cpa16(sH_u32 + row * (SHS * 2) + bcol,
                      (const char*)h_in + (size_t)row * (HID * 2) + bcol);
            }
            cpa_commit();
        }

        // prefetch xg operands for the cell update (overlaps fill + GEMM)
        float xr[2][4];
#pragma unroll
        for (int q = 0; q < 2; q++) {
            int idx = q * 256 + tid;
            int bb = idx >> 3, jj = idx & 7;
#pragma unroll
            for (int g = 0; g < 4; g++)
                xr[q][g] = __ldg(&xg_t[(size_t)bb * G4 + (g << 10) + j0 + jj]);
        }

        wmma::fragment<wmma::accumulator, 16, 16, 16, float> acc[2][2];
        wmma::fill_fragment(acc[0][0], 0.0f);
        wmma::fill_fragment(acc[0][1], 0.0f);
        wmma::fill_fragment(acc[1][0], 0.0f);
        wmma::fill_fragment(acc[1][1], 0.0f);

        // per-warp progressive pipeline: no CTA-wide syncs in the GEMM
        STEP_SUBQ(0, 3);
        STEP_SUBQ(1, 2);
        STEP_SUBQ(2, 1);
        STEP_SUBQ(3, 0);

        // all warps done reading sH -> safe to overlay partials onto it
        __syncthreads();
        {
            float* dst = sGp + kgrp * (64 * SGP);
#pragma unroll
            for (int mt = 0; mt < 2; mt++)
#pragma unroll
                for (int nt = 0; nt < 2; nt++)
                    wmma::store_matrix_sync(dst + (mhalf + mt * 16) * SGP + nt * 16,
                                            acc[mt][nt], SGP, wmma::mem_row_major);
        }
        __syncthreads();

        // cell update: sum 4 k-partials + xg; c fp32 regs; h_out bf16;
        // hs fp32; g_xa tf32 (feeds layer-2 projection, no conv pass needed)
#pragma unroll
        for (int q = 0; q < 2; q++) {
            int idx = q * 256 + tid;
            int bb = idx >> 3, jj = idx & 7;
            int j  = j0 + jj;
            float gi = xr[q][0], gf = xr[q][1], gg = xr[q][2], go = xr[q][3];
#pragma unroll
            for (int g = 0; g < 4; g++) {
                const float* p = sGp + g * (64 * SGP) + bb * SGP;
                gi += p[jj];
                gf += p[8 + jj];
                gg += p[16 + jj];
                go += p[24 + jj];
            }
            float cn = sigm(gf) * creg[q] + sigm(gi) * tanhf(gg);
            float hn = sigm(go) * tanhf(cn);
            creg[q] = cn;
            h_out[bb * HID + j] = __float2bfloat16_rn(hn);
            hs[((size_t)bb * SEQ + t) * HID + j] = hn;
            g_xa[((size_t)bb * SEQ + t) * HID + j] = totf32(hn);
            if (t == SEQ - 1) {
                hT[bb * HID + j] = hn;
                cT[bb * HID + j] = cn;
            }
        }

        // device-wide barrier: order all h_out stores before any CTA proceeds.
        // Hard poll fast path; bounded backoff guards against livelock.
        __threadfence();
        __syncthreads();
        if (tid == 0) {
            atomicAdd(&g_bar, 1u);
            int spins = 0;
            while (*(volatile unsigned*)&g_bar < target) {
                if (++spins > 8192) __nanosleep(64);
            }
        }
        __syncthreads();
        target += NCTA;
    }
}

// ---------------------------------------------------------------------------
extern "C" void kernel_launch(void* const* d_in, const int* in_sizes, int n_in,
                              void* d_out, int out_size) {
    (void)in_sizes; (void)n_in; (void)out_size;
    const float* x     = (const float*)d_in[0];
    const float* Wx[2] = {(const float*)d_in[1], (const float*)d_in[5]};
    const float* bx[2] = {(const float*)d_in[2], (const float*)d_in[6]};
    const float* Wh[2] = {(const float*)d_in[3], (const float*)d_in[7]};
    const float* bh[2] = {(const float*)d_in[4], (const float*)d_in[8]};

    float* out = (float*)d_out;
    float* hs  = out;                          // (B,S,H): layer0 scratch, then final layer1 output
    float* hT  = out + OUT_ELEMS;              // (L,B,H)
    float* cT  = hT + 2 * BATCH * HID;         // (L,B,H)

    static int attr_set = 0;
    if (!attr_set) {
        cudaFuncSetAttribute(lstm_seq_kernel, cudaFuncAttributeMaxDynamicSharedMemorySize,
                             LS_SMEM_BYTES);
        cudaFuncSetAttribute(proj_wmma_kernel, cudaFuncAttributeMaxDynamicSharedMemorySize,
                             PJ_SMEM_BYTES);
        attr_set = 1;
    }

    dim3 tgrid(G4 / PN, (BATCH * SEQ) / PM);   // (32, 256)

    for (int l = 0; l < 2; l++) {
        if (l == 0)
            conv_a_kernel<<<(int)(OUT_ELEMS / 1024), 256>>>(x);
        conv_w_kernel<<<(HID * G4) / 1024, 256>>>(Wx[l]);      // + g_bar/g_hbuf reset
        proj_wmma_kernel<<<tgrid, 256, PJ_SMEM_BYTES>>>(bx[l], bh[l]);
        lstm_seq_kernel<<<NCTA, 256, LS_SMEM_BYTES>>>(
            Wh[l], hs, hT + l * BATCH * HID, cT + l * BATCH * HID);
    }
}

// round 13
// speedup vs baseline: 3.4747x; 1.0046x over previous
#include <cuda_runtime.h>
#include <cuda_bf16.h>
#include <mma.h>
#include <cstdint>
#include <cstddef>

using namespace nvcuda;

#define BATCH 64
#define SEQ   512
#define HID   1024
#define G4    4096
#define NCTA  128
#define OUT_ELEMS ((size_t)BATCH * SEQ * HID)

// Scratch (device globals — no allocation allowed).
static __device__ float g_xg[(size_t)SEQ * BATCH * G4];          // [t][b][g]
static __device__ float g_xa[(size_t)BATCH * SEQ * HID];         // tf32-rounded activations
static __device__ float g_wr[(size_t)HID * G4];                  // tf32-rounded W [k][n]
static __device__ __nv_bfloat16 g_hbuf[2][BATCH * HID];          // ping-pong hidden (bf16)
static __device__ unsigned g_bar;                                // grid barrier counter

__device__ __forceinline__ float sigm(float x) { return 1.0f / (1.0f + __expf(-x)); }

__device__ __forceinline__ void cpa16(uint32_t smem_dst, const void* gsrc) {
    asm volatile("cp.async.cg.shared.global [%0], [%1], 16;" :: "r"(smem_dst), "l"(gsrc));
}
__device__ __forceinline__ void cpa_commit() { asm volatile("cp.async.commit_group;"); }
__device__ __forceinline__ void cpa_wait0()  { asm volatile("cp.async.wait_group 0;" ::: "memory"); }

__device__ __forceinline__ float totf32(float x) {
    unsigned u;
    asm("cvt.rna.tf32.f32 %0, %1;" : "=r"(u) : "f"(x));
    return __uint_as_float(u);
}

// ---------------------------------------------------------------------------
// Pre-pass 1: elementwise tf32 rounding of activations -> g_xa (layer 0 only).
// ---------------------------------------------------------------------------
__global__ __launch_bounds__(256) void conv_a_kernel(const float* __restrict__ in) {
    size_t i = (size_t)blockIdx.x * 256 + threadIdx.x;
    float4 v = ((const float4*)in)[i];
    v.x = totf32(v.x); v.y = totf32(v.y); v.z = totf32(v.z); v.w = totf32(v.w);
    ((float4*)g_xa)[i] = v;
}

// ---------------------------------------------------------------------------
// Pre-pass 2: tf32 rounding of W [k][n] -> g_wr, PLUS per-layer state reset
// (g_bar and g_hbuf[0]) folded in — runs before every lstm launch.
// ---------------------------------------------------------------------------
__global__ __launch_bounds__(256) void conv_w_kernel(const float* __restrict__ W) {
    size_t i = (size_t)blockIdx.x * 256 + threadIdx.x;
    float4 v = ((const float4*)W)[i];
    v.x = totf32(v.x); v.y = totf32(v.y); v.z = totf32(v.z); v.w = totf32(v.w);
    ((float4*)g_wr)[i] = v;
    if (i == 0) g_bar = 0u;
    if (i < (BATCH * HID) / 2) ((uint32_t*)g_hbuf[0])[i] = 0u;   // 2 bf16 zeros
}

// ---------------------------------------------------------------------------
// wmma-tf32 projection (unchanged from the passing round-7..12 version).
// ---------------------------------------------------------------------------
#define PM 128
#define PN 128
#define PKC 32
#define SA_STR 36
#define SB_STR 132
#define PSTG (PM * SA_STR + PKC * SB_STR)        // 8832 floats
#define EP_STR 132
#define PJ_SMEM_FLOATS (2 * PSTG + PN)
#define PJ_SMEM_BYTES (PJ_SMEM_FLOATS * 4)       // 71168 B

__device__ __forceinline__ void proj_fill(uint32_t stg_u32,
                                          const float* __restrict__ a_r0,
                                          const float* __restrict__ w_c0,
                                          int k0, int tid) {
    uint32_t aB = stg_u32;
    uint32_t bB = stg_u32 + PM * SA_STR * 4;
#pragma unroll
    for (int i = 0; i < 4; i++) {
        int u = tid + 256 * i;
        int r = u >> 3, f = u & 7;
        cpa16(aB + (r * SA_STR + f * 4) * 4, a_r0 + (size_t)r * HID + k0 + f * 4);
    }
#pragma unroll
    for (int i = 0; i < 4; i++) {
        int u = tid + 256 * i;
        int r = u >> 5, f = u & 31;
        cpa16(bB + (r * SB_STR + f * 4) * 4, w_c0 + (size_t)(k0 + r) * G4 + f * 4);
    }
}

__global__ __launch_bounds__(256, 2) void proj_wmma_kernel(const float* __restrict__ bx,
                                                           const float* __restrict__ bh) {
    extern __shared__ float ps[];
    float* sBias = ps + 2 * PSTG;

    const int tid = threadIdx.x;
    const int wid = tid >> 5;
    const int wm  = wid & 3;
    const int wn  = wid >> 2;

    const int col0 = blockIdx.x * PN;
    const int row0 = blockIdx.y * PM;

    const uint32_t ps_u32 = (uint32_t)__cvta_generic_to_shared(ps);
    const float* a_r0 = g_xa + (size_t)row0 * HID;
    const float* w_c0 = g_wr + col0;

    if (tid < PN) sBias[tid] = bx[col0 + tid] + bh[col0 + tid];

    wmma::fragment<wmma::accumulator, 16, 16, 8, float> acc[2][4];
#pragma unroll
    for (int mt = 0; mt < 2; mt++)
#pragma unroll
        for (int nt = 0; nt < 4; nt++) wmma::fill_fragment(acc[mt][nt], 0.0f);

    proj_fill(ps_u32, a_r0, w_c0, 0, tid);
    cpa_commit();
    cpa_wait0();
    __syncthreads();

#pragma unroll 1
    for (int c = 0; c < HID / PKC; c++) {
        const int cs = c & 1, ns = cs ^ 1;
        const float* sA = ps + cs * PSTG;
        const float* sB = sA + PM * SA_STR;

        if (c < HID / PKC - 1) {
            proj_fill(ps_u32 + ns * PSTG * 4, a_r0, w_c0, (c + 1) * PKC, tid);
            cpa_commit();
        }

#pragma unroll
        for (int kt = 0; kt < 4; kt++) {
            wmma::fragment<wmma::matrix_a, 16, 16, 8, wmma::precision::tf32, wmma::row_major> af[2];
            wmma::load_matrix_sync(af[0], sA + (wm * 32 +  0) * SA_STR + kt * 8, SA_STR);
            wmma::load_matrix_sync(af[1], sA + (wm * 32 + 16) * SA_STR + kt * 8, SA_STR);
#pragma unroll
            for (int nt = 0; nt < 4; nt++) {
                wmma::fragment<wmma::matrix_b, 16, 16, 8, wmma::precision::tf32, wmma::row_major> bf;
                wmma::load_matrix_sync(bf, sB + (kt * 8) * SB_STR + wn * 64 + nt * 16, SB_STR);
                wmma::mma_sync(acc[0][nt], af[0], bf, acc[0][nt]);
                wmma::mma_sync(acc[1][nt], af[1], bf, acc[1][nt]);
            }
        }

        cpa_wait0();
        __syncthreads();
    }

    float* sEpi = ps;
#pragma unroll
    for (int mt = 0; mt < 2; mt++)
#pragma unroll
        for (int nt = 0; nt < 4; nt++)
            wmma::store_matrix_sync(sEpi + (wm * 32 + mt * 16) * EP_STR + wn * 64 + nt * 16,
                                    acc[mt][nt], EP_STR, wmma::mem_row_major);
    __syncthreads();

    const int r    = tid >> 1;
    const int half = (tid & 1) * 64;
    const int m = row0 + r;
    const int b = m >> 9;
    const int s = m & (SEQ - 1);
    float* dst = &g_xg[((size_t)s * BATCH + b) * G4 + col0 + half];
#pragma unroll
    for (int j = 0; j < 64; j += 4) {
        float4 v = *(float4*)&sEpi[r * EP_STR + half + j];
        v.x += sBias[half + j + 0];
        v.y += sBias[half + j + 1];
        v.z += sBias[half + j + 2];
        v.w += sBias[half + j + 3];
        *(float4*)&dst[j] = v;
    }
}

// ---------------------------------------------------------------------------
// Persistent recurrence kernel: 512-thread warp-private K-split edition.
// 128 CTAs (1/SM). CTA owns j in [j0,j0+8) -> 32 gate cols. sWh [1024][40] bf16
// resident all layer. 16 warps = 8 K-groups x 2 M-halves; warp tile 32x32 =
// 2x2 fragments over a 128-k slice. Each warp cp.async-fills ONLY its own sH
// region (32 rows x 128 k, 2 sub-commits) -> no CTA syncs in the GEMM.
// K-partials (8 x [64][36] fp32) overlay sH (dead after MMA reads). 2x the
// warps of round 12 for latency hiding (occ 12.5% -> 25%).
// ---------------------------------------------------------------------------
#define SWS 40
#define SHS 1032
#define SGP 36
#define LS_WH_BYTES (HID * SWS * 2)                   // 81920
#define LS_H_BYTES  (64 * SHS * 2)                    // 132096
#define LS_SMEM_BYTES (LS_WH_BYTES + LS_H_BYTES)      // 214016

// one k-sub-half: wait own fills, then 4 k16 of 2x2 mma
#define STEP_SUBQ(sq, waitn)                                                         \
    do {                                                                             \
        asm volatile("cp.async.wait_group " #waitn ";" ::: "memory");                \
        __syncwarp();                                                                \
        _Pragma("unroll")                                                            \
        for (int j = 0; j < 4; j++) {                                                \
            const int k16 = kgrp * 8 + (sq) * 4 + j;                                 \
            wmma::fragment<wmma::matrix_a, 16, 16, 16, __nv_bfloat16, wmma::row_major> a0, a1; \
            wmma::fragment<wmma::matrix_b, 16, 16, 16, __nv_bfloat16, wmma::row_major> b0, b1; \
            wmma::load_matrix_sync(a0, sH + (mhalf +  0) * SHS + k16 * 16, SHS);     \
            wmma::load_matrix_sync(a1, sH + (mhalf + 16) * SHS + k16 * 16, SHS);     \
            wmma::load_matrix_sync(b0, sWh + (k16 * 16) * SWS +  0, SWS);            \
            wmma::load_matrix_sync(b1, sWh + (k16 * 16) * SWS + 16, SWS);            \
            wmma::mma_sync(acc[0][0], a0, b0, acc[0][0]);                            \
            wmma::mma_sync(acc[0][1], a0, b1, acc[0][1]);                            \
            wmma::mma_sync(acc[1][0], a1, b0, acc[1][0]);                            \
            wmma::mma_sync(acc[1][1], a1, b1, acc[1][1]);                            \
        }                                                                            \
    } while (0)

__global__ __launch_bounds__(512, 1) void lstm_seq_kernel(const float* __restrict__ Wh,
                                                          float* __restrict__ hs,
                                                          float* __restrict__ hT,
                                                          float* __restrict__ cT,
                                                          int write_xa) {
    extern __shared__ char smc[];
    __nv_bfloat16* sWh = (__nv_bfloat16*)smc;                       // [1024][40]
    __nv_bfloat16* sH  = (__nv_bfloat16*)(smc + LS_WH_BYTES);       // [64][1032]
    float*         sGp = (float*)(smc + LS_WH_BYTES);               // overlay: [8][64][36]

    const int tid  = threadIdx.x;
    const int wid  = tid >> 5;
    const int lane = tid & 31;
    const int j0   = blockIdx.x * 8;

    // Wh slice fill, bf16-rounded (once per layer)
#pragma unroll 2
    for (int it = 0; it < 64; it++) {
        int idx = it * 512 + tid;
        int c = idx & 31, k = idx >> 5;
        int gcol = ((c >> 3) << 10) + j0 + (c & 7);
        sWh[k * SWS + c] = __float2bfloat16_rn(Wh[(size_t)k * G4 + gcol]);
    }

    const int kgrp  = wid >> 1;               // k-eighth this warp owns (0..7)
    const int mhalf = (wid & 1) * 32;         // M rows this warp owns
    const uint32_t sH_u32 = (uint32_t)__cvta_generic_to_shared(sH);

    float creg = 0.0f;
    __syncthreads();

    unsigned target = NCTA;
    for (int t = 0; t < SEQ; t++) {
        const __nv_bfloat16* __restrict__ h_in = g_hbuf[t & 1];
        __nv_bfloat16* __restrict__ h_out      = g_hbuf[(t & 1) ^ 1];
        const float* __restrict__ xg_t = g_xg + (size_t)t * BATCH * G4;

        // warp-private fill: 32 rows x 128 k, as 2 sub-commits of 64 k each
#pragma unroll
        for (int sq = 0; sq < 2; sq++) {
#pragma unroll
            for (int i = 0; i < 8; i++) {
                int idx = i * 32 + lane;                  // 0..255
                int row = mhalf + (idx >> 3);
                int bcol = kgrp * 256 + sq * 128 + (idx & 7) * 16;   // bytes
                cpa16(sH_u32 + row * (SHS * 2) + bcol,
                      (const char*)h_in + (size_t)row * (HID * 2) + bcol);
            }
            cpa_commit();
        }

        // prefetch xg operands for the cell update (overlaps fill + GEMM)
        const int bb = tid >> 3, jj = tid & 7;
        float xr[4];
#pragma unroll
        for (int g = 0; g < 4; g++)
            xr[g] = __ldg(&xg_t[(size_t)bb * G4 + (g << 10) + j0 + jj]);

        wmma::fragment<wmma::accumulator, 16, 16, 16, float> acc[2][2];
        wmma::fill_fragment(acc[0][0], 0.0f);
        wmma::fill_fragment(acc[0][1], 0.0f);
        wmma::fill_fragment(acc[1][0], 0.0f);
        wmma::fill_fragment(acc[1][1], 0.0f);

        // per-warp progressive pipeline: no CTA-wide syncs in the GEMM
        STEP_SUBQ(0, 1);
        STEP_SUBQ(1, 0);

        // all warps done reading sH -> safe to overlay partials onto it
        __syncthreads();
        {
            float* dst = sGp + kgrp * (64 * SGP);
#pragma unroll
            for (int mt = 0; mt < 2; mt++)
#pragma unroll
                for (int nt = 0; nt < 2; nt++)
                    wmma::store_matrix_sync(dst + (mhalf + mt * 16) * SGP + nt * 16,
                                            acc[mt][nt], SGP, wmma::mem_row_major);
        }
        __syncthreads();

        // cell update: sum 8 k-partials + xg; c fp32 reg; h_out bf16;
        // hs fp32; g_xa tf32 (only when a next layer consumes it)
        {
            int j = j0 + jj;
            float gi = xr[0], gf = xr[1], gg = xr[2], go = xr[3];
#pragma unroll
            for (int g = 0; g < 8; g++) {
                const float* p = sGp + g * (64 * SGP) + bb * SGP;
                gi += p[jj];
                gf += p[8 + jj];
                gg += p[16 + jj];
                go += p[24 + jj];
            }
            float cn = sigm(gf) * creg + sigm(gi) * tanhf(gg);
            float hn = sigm(go) * tanhf(cn);
            creg = cn;
            h_out[bb * HID + j] = __float2bfloat16_rn(hn);
            hs[((size_t)bb * SEQ + t) * HID + j] = hn;
            if (write_xa)
                g_xa[((size_t)bb * SEQ + t) * HID + j] = totf32(hn);
            if (t == SEQ - 1) {
                hT[bb * HID + j] = hn;
                cT[bb * HID + j] = cn;
            }
        }

        // device-wide barrier: order all h_out stores before any CTA proceeds.
        __threadfence();
        __syncthreads();
        if (tid == 0) {
            atomicAdd(&g_bar, 1u);
            int spins = 0;
            while (*(volatile unsigned*)&g_bar < target) {
                if (++spins > 8192) __nanosleep(64);
            }
        }
        __syncthreads();
        target += NCTA;
    }
}

// ---------------------------------------------------------------------------
extern "C" void kernel_launch(void* const* d_in, const int* in_sizes, int n_in,
                              void* d_out, int out_size) {
    (void)in_sizes; (void)n_in; (void)out_size;
    const float* x     = (const float*)d_in[0];
    const float* Wx[2] = {(const float*)d_in[1], (const float*)d_in[5]};
    const float* bx[2] = {(const float*)d_in[2], (const float*)d_in[6]};
    const float* Wh[2] = {(const float*)d_in[3], (const float*)d_in[7]};
    const float* bh[2] = {(const float*)d_in[4], (const float*)d_in[8]};

    float* out = (float*)d_out;
    float* hs  = out;                          // (B,S,H): layer0 scratch, then final layer1 output
    float* hT  = out + OUT_ELEMS;              // (L,B,H)
    float* cT  = hT + 2 * BATCH * HID;         // (L,B,H)

    static int attr_set = 0;
    if (!attr_set) {
        cudaFuncSetAttribute(lstm_seq_kernel, cudaFuncAttributeMaxDynamicSharedMemorySize,
                             LS_SMEM_BYTES);
        cudaFuncSetAttribute(proj_wmma_kernel, cudaFuncAttributeMaxDynamicSharedMemorySize,
                             PJ_SMEM_BYTES);
        attr_set = 1;
    }

    dim3 tgrid(G4 / PN, (BATCH * SEQ) / PM);   // (32, 256)

    for (int l = 0; l < 2; l++) {
        if (l == 0)
            conv_a_kernel<<<(int)(OUT_ELEMS / 1024), 256>>>(x);
        conv_w_kernel<<<(HID * G4) / 1024, 256>>>(Wx[l]);      // + g_bar/g_hbuf reset
        proj_wmma_kernel<<<tgrid, 256, PJ_SMEM_BYTES>>>(bx[l], bh[l]);
        lstm_seq_kernel<<<NCTA, 512, LS_SMEM_BYTES>>>(
            Wh[l], hs, hT + l * BATCH * HID, cT + l * BATCH * HID,
            l == 0 ? 1 : 0);
    }
}